// round 5
// baseline (speedup 1.0000x reference)
#include <cuda_runtime.h>
#include <cuda_bf16.h>
#include <cstdint>

// ---------------- problem constants ----------------
#define N_TOK  16384
#define DDIM   512
#define FDIM   2048
#define NEXP   8
#define CAP    16384.0f
#define EPSV   1e-6f

#define PAD_ROWS (N_TOK + NEXP * 128)   // 17408
#define MAX_TILES (PAD_ROWS / 128)      // 136

// ---------------- scratch (device globals; 16B-access aligned) ----------------
__device__ unsigned char g_expert[N_TOK];
__device__ float g_logit[N_TOK];
__device__ float g_denom_inv[NEXP];
__device__ int   g_off[NEXP + 1];
__device__ int   g_ctr[NEXP];
__device__ int   g_perm[PAD_ROWS];

__device__ __align__(256) __nv_bfloat16 g_Xhi[(size_t)PAD_ROWS * DDIM];
__device__ __align__(256) __nv_bfloat16 g_Xlo[(size_t)PAD_ROWS * DDIM];
__device__ __align__(256) __nv_bfloat16 g_Hhi[(size_t)PAD_ROWS * FDIM];
__device__ __align__(256) __nv_bfloat16 g_Hlo[(size_t)PAD_ROWS * FDIM];
__device__ __align__(256) __nv_bfloat16 g_W1Thi[(size_t)NEXP * FDIM * DDIM];  // [E][F][D]
__device__ __align__(256) __nv_bfloat16 g_W1Tlo[(size_t)NEXP * FDIM * DDIM];
__device__ __align__(256) __nv_bfloat16 g_W2Thi[(size_t)NEXP * DDIM * FDIM];  // [E][D][F]
__device__ __align__(256) __nv_bfloat16 g_W2Tlo[(size_t)NEXP * DDIM * FDIM];

// ---------------- helpers ----------------
__device__ __forceinline__ uint32_t smem_to_u32(const void* smem_ptr) {
    uint32_t addr;
    asm("{ .reg .u64 tmp; cvta.to.shared.u64 tmp, %1; cvt.u32.u64 %0, tmp; }"
        : "=r"(addr) : "l"(smem_ptr));
    return addr;
}

#define SMEM_SWIZZLE_128B(byte_offset) \
    ((byte_offset) ^ (((byte_offset) >> 3) & 0x70))

__device__ __forceinline__ void cp16(uint32_t dst, const void* src) {
    asm volatile("cp.async.cg.shared.global [%0], [%1], 16;"
                 :: "r"(dst), "l"(src) : "memory");
}
#define CP_COMMIT()  asm volatile("cp.async.commit_group;" ::: "memory")
#define CP_WAIT_1()  asm volatile("cp.async.wait_group 1;" ::: "memory")
#define CP_WAIT_0()  asm volatile("cp.async.wait_group 0;" ::: "memory")

__device__ __forceinline__ void ldsm_x4(uint32_t& r0, uint32_t& r1, uint32_t& r2,
                                        uint32_t& r3, uint32_t addr) {
    asm volatile("ldmatrix.sync.aligned.m8n8.x4.shared.b16 {%0,%1,%2,%3}, [%4];"
                 : "=r"(r0), "=r"(r1), "=r"(r2), "=r"(r3) : "r"(addr));
}
__device__ __forceinline__ void mma16816(float* d, const uint32_t* a,
                                         uint32_t b0, uint32_t b1) {
    asm volatile(
        "mma.sync.aligned.m16n8k16.row.col.f32.bf16.bf16.f32 "
        "{%0,%1,%2,%3},{%4,%5,%6,%7},{%8,%9},{%0,%1,%2,%3};"
        : "+f"(d[0]), "+f"(d[1]), "+f"(d[2]), "+f"(d[3])
        : "r"(a[0]), "r"(a[1]), "r"(a[2]), "r"(a[3]), "r"(b0), "r"(b1));
}

// ---------------------------------------------------------------------------
// 0) reset perm
// ---------------------------------------------------------------------------
__global__ void init_perm_kernel() {
    int i = blockIdx.x * blockDim.x + threadIdx.x;
    if (i < PAD_ROWS) g_perm[i] = -1;
}

// ---------------------------------------------------------------------------
// 1) router: logits = x @ Wg^T, top-1 per token (one warp per token)
// ---------------------------------------------------------------------------
__global__ __launch_bounds__(256) void router_kernel(const float* __restrict__ x,
                                                     const float* __restrict__ Wg) {
    __shared__ float sWg[NEXP * DDIM];
    int tid = threadIdx.x;
    for (int i = tid; i < NEXP * DDIM; i += 256) sWg[i] = Wg[i];
    __syncthreads();

    int warp = tid >> 5, lane = tid & 31;
    int token = blockIdx.x * 8 + warp;
    if (token >= N_TOK) return;

    const float* xr = x + (size_t)token * DDIM;
    float acc[NEXP];
#pragma unroll
    for (int e = 0; e < NEXP; e++) acc[e] = 0.f;
    for (int k = lane; k < DDIM; k += 32) {
        float xv = xr[k];
#pragma unroll
        for (int e = 0; e < NEXP; e++) acc[e] += xv * sWg[e * DDIM + k];
    }
#pragma unroll
    for (int e = 0; e < NEXP; e++) {
#pragma unroll
        for (int off = 16; off > 0; off >>= 1)
            acc[e] += __shfl_xor_sync(0xFFFFFFFF, acc[e], off);
    }
    if (lane == 0) {
        int best = 0;
#pragma unroll
        for (int e = 1; e < NEXP; e++)
            if (acc[e] > acc[best]) best = e;
        g_expert[token] = (unsigned char)best;
        g_logit[token]  = acc[best];
    }
}

// ---------------------------------------------------------------------------
// 2) setup (single block, deterministic tree reduction)
// ---------------------------------------------------------------------------
__global__ __launch_bounds__(256) void setup_kernel() {
    __shared__ float sden[NEXP][256];
    __shared__ int   scnt[NEXP][256];
    int tid = threadIdx.x;

    float den[NEXP]; int cnt[NEXP];
#pragma unroll
    for (int e = 0; e < NEXP; e++) { den[e] = 0.f; cnt[e] = 0; }
    for (int t = tid; t < N_TOK; t += 256) {
        int e = g_expert[t];
        den[e] += g_logit[t];
        cnt[e]++;
    }
#pragma unroll
    for (int e = 0; e < NEXP; e++) { sden[e][tid] = den[e]; scnt[e][tid] = cnt[e]; }
    __syncthreads();
    for (int s = 128; s > 0; s >>= 1) {
        if (tid < s) {
#pragma unroll
            for (int e = 0; e < NEXP; e++) {
                sden[e][tid] += sden[e][tid + s];
                scnt[e][tid] += scnt[e][tid + s];
            }
        }
        __syncthreads();
    }
    if (tid == 0) {
        int off = 0;
        for (int e = 0; e < NEXP; e++) {
            g_denom_inv[e] = CAP / (sden[e][0] + EPSV);
            g_off[e] = off;
            g_ctr[e] = off;
            off += ((scnt[e][0] + 127) >> 7) << 7;
        }
        g_off[NEXP] = off;
    }
}

// ---------------------------------------------------------------------------
// 3) scatter
// ---------------------------------------------------------------------------
__global__ void scatter_kernel() {
    int t = blockIdx.x * blockDim.x + threadIdx.x;
    if (t >= N_TOK) return;
    int e = g_expert[t];
    int pos = atomicAdd(&g_ctr[e], 1);
    g_perm[pos] = t;
}

// ---------------------------------------------------------------------------
// 4) gather x into sorted order + split to bf16 hi/lo
// ---------------------------------------------------------------------------
__global__ __launch_bounds__(128) void gather_x_kernel(const float* __restrict__ x) {
    int r = blockIdx.x;
    int t = threadIdx.x;
    int tok = g_perm[r];
    float4 v = make_float4(0.f, 0.f, 0.f, 0.f);
    if (tok >= 0) v = *(const float4*)(x + (size_t)tok * DDIM + t * 4);

    __nv_bfloat162 h0 = __float22bfloat162_rn(make_float2(v.x, v.y));
    __nv_bfloat162 h1 = __float22bfloat162_rn(make_float2(v.z, v.w));
    float2 l0f = make_float2(v.x - __bfloat162float(__low2bfloat16(h0)),
                             v.y - __bfloat162float(__high2bfloat16(h0)));
    float2 l1f = make_float2(v.z - __bfloat162float(__low2bfloat16(h1)),
                             v.w - __bfloat162float(__high2bfloat16(h1)));
    __nv_bfloat162 l0 = __float22bfloat162_rn(l0f);
    __nv_bfloat162 l1 = __float22bfloat162_rn(l1f);

    size_t off = (size_t)r * DDIM + t * 4;
    uint2 hh, ll;
    hh.x = *(uint32_t*)&h0; hh.y = *(uint32_t*)&h1;
    ll.x = *(uint32_t*)&l0; ll.y = *(uint32_t*)&l1;
    *(uint2*)(g_Xhi + off) = hh;
    *(uint2*)(g_Xlo + off) = ll;
}

// ---------------------------------------------------------------------------
// 5) transpose+split weights: in [E][R][C] fp32 -> out [E][C][R] bf16 hi/lo
// ---------------------------------------------------------------------------
__global__ __launch_bounds__(256) void trans_conv_kernel(const float* __restrict__ in,
                                                         int R, int C, int which) {
    __shared__ float tile[32][33];
    __nv_bfloat16* hiOut = which ? g_W2Thi : g_W1Thi;
    __nv_bfloat16* loOut = which ? g_W2Tlo : g_W1Tlo;

    int e  = blockIdx.z;
    int c0 = blockIdx.x * 32;
    int r0 = blockIdx.y * 32;
    int tx = threadIdx.x & 31;
    int ty8 = threadIdx.x >> 5;

    const float* src = in + ((size_t)e * R + r0) * C + c0;
#pragma unroll
    for (int i = 0; i < 32; i += 8)
        tile[ty8 + i][tx] = src[(size_t)(ty8 + i) * C + tx];
    __syncthreads();

    size_t ob = ((size_t)e * C + c0) * R + r0;
#pragma unroll
    for (int i = 0; i < 32; i += 8) {
        float f = tile[tx][ty8 + i];
        __nv_bfloat16 h = __float2bfloat16(f);
        __nv_bfloat16 l = __float2bfloat16(f - __bfloat162float(h));
        hiOut[ob + (size_t)(ty8 + i) * R + tx] = h;
        loOut[ob + (size_t)(ty8 + i) * R + tx] = l;
    }
}

// ---------------------------------------------------------------------------
// HMMA grouped GEMM:  C[128 x 256 tile] = A[128 x KTOT] @ B^T  (B: [N][K] K-major)
// bf16 3-pass split precision; cp.async 2-stage pipeline; ldmatrix + mma.sync.
// 8 warps, warp tile 64 x 64 (2 m-warps x 4 n-warps).
//   FINAL=false: A = g_X (sorted), B = W1T, epilogue relu(+b1) -> g_H hi/lo
//   FINAL=true : A = g_H,          B = W2T, epilogue scale*(+b2) -> scatter to out
//
// smem per stage (96KB): Ahi 16K | Alo 16K | Bhi 32K | Blo 32K
// dynamic layout: [0,512) token ids (FINAL) | [1024 + p*98304) stages
// ---------------------------------------------------------------------------
#define STAGE_BYTES 98304
#define SMEM_GEMM_BYTES (1024 + 2 * STAGE_BYTES)   // 197632

template<int KTOT, bool FINAL>
__global__ __launch_bounds__(256, 1) void moe_gemm_kernel(
    const float* __restrict__ bias,   // [E][NTOT]
    float* __restrict__ fout)         // FINAL: [N_TOK][DDIM]
{
    constexpr int NTOT = FINAL ? DDIM : FDIM;
    extern __shared__ char smem[];
    uint32_t sbase = smem_to_u32(smem);
    int tid = threadIdx.x;
    int lane = tid & 31, wid = tid >> 5;

    int row0 = blockIdx.x * 128;
    int total = g_off[NEXP];
    if (row0 >= total) return;
    int e = 0;
    while (g_off[e + 1] <= row0) e++;
    int bn = blockIdx.y * 256;

    if (FINAL && tid < 128) ((int*)smem)[tid] = g_perm[row0 + tid];

    const __nv_bfloat16* Ahi = (FINAL ? g_Hhi : g_Xhi) + (size_t)row0 * KTOT;
    const __nv_bfloat16* Alo = (FINAL ? g_Hlo : g_Xlo) + (size_t)row0 * KTOT;
    const __nv_bfloat16* Bhi = (FINAL ? g_W2Thi : g_W1Thi) + ((size_t)e * NTOT + bn) * KTOT;
    const __nv_bfloat16* Blo = (FINAL ? g_W2Tlo : g_W1Tlo) + ((size_t)e * NTOT + bn) * KTOT;

    const int nC = KTOT / 64;

    // warp tile: 64 (m) x 64 (n); warps laid out 2 (m) x 4 (n)
    int wm = (wid & 1) * 64;
    int wn = (wid >> 1) * 64;

    float acc[4][8][4];
#pragma unroll
    for (int mi = 0; mi < 4; mi++)
#pragma unroll
        for (int ni = 0; ni < 8; ni++)
#pragma unroll
            for (int q = 0; q < 4; q++) acc[mi][ni][q] = 0.f;

    // --- async load of one 64-wide K chunk into stage p ---
    auto load_chunk = [&](int c, int p) {
        int kt = c * 64;
        uint32_t base = sbase + 1024 + p * STAGE_BYTES;
        // A: 128 rows -> 1024 16B units per array
#pragma unroll
        for (int i = 0; i < 4; i++) {
            int u = tid + i * 256;
            int r = u >> 3, s = u & 7;
            uint32_t sw = SMEM_SWIZZLE_128B((uint32_t)(r * 128 + s * 16));
            size_t goff = (size_t)r * KTOT + kt + s * 8;
            cp16(base +         sw, Ahi + goff);
            cp16(base + 16384 + sw, Alo + goff);
        }
        // B: 256 rows -> 2048 16B units per array
#pragma unroll
        for (int i = 0; i < 8; i++) {
            int u = tid + i * 256;
            int r = u >> 3, s = u & 7;
            uint32_t sw = SMEM_SWIZZLE_128B((uint32_t)(r * 128 + s * 16));
            size_t goff = (size_t)r * KTOT + kt + s * 8;
            cp16(base + 32768 + sw, Bhi + goff);
            cp16(base + 65536 + sw, Blo + goff);
        }
    };

    // --- compute one staged chunk (4 k-steps of 16) ---
    auto compute_chunk = [&](int p) {
        uint32_t st = sbase + 1024 + p * STAGE_BYTES;
#pragma unroll
        for (int ks = 0; ks < 4; ks++) {
            int k0 = ks * 16;
            int colb = (k0 + (lane >> 4) * 8) * 2;

            uint32_t Ah[4][4], Al[4][4];
#pragma unroll
            for (int mi = 0; mi < 4; mi++) {
                int row = wm + mi * 16 + (lane & 15);
                uint32_t off = SMEM_SWIZZLE_128B((uint32_t)(row * 128 + colb));
                ldsm_x4(Ah[mi][0], Ah[mi][1], Ah[mi][2], Ah[mi][3], st + off);
                ldsm_x4(Al[mi][0], Al[mi][1], Al[mi][2], Al[mi][3], st + 16384 + off);
            }
            // B: one x4 covers two n-tiles (ni=2nj: r0/r2, ni=2nj+1: r1/r3)
            uint32_t Bh[2][4], Bl[2][4];
#pragma unroll
            for (int nj = 0; nj < 2; nj++) {
                int row = wn + nj * 16 + (lane & 15);
                uint32_t off = SMEM_SWIZZLE_128B((uint32_t)(row * 128 + colb));
                ldsm_x4(Bh[nj][0], Bh[nj][1], Bh[nj][2], Bh[nj][3], st + 32768 + off);
                ldsm_x4(Bl[nj][0], Bl[nj][1], Bl[nj][2], Bl[nj][3], st + 65536 + off);
            }
            // note: only 2 nj pairs cover ni 0..3; upper half uses nj 0..1 of
            // the second 32-row group => loop nj 0..3 over 64 n rows:
            uint32_t Bh2[2][4], Bl2[2][4];
#pragma unroll
            for (int nj = 0; nj < 2; nj++) {
                int row = wn + 32 + nj * 16 + (lane & 15);
                uint32_t off = SMEM_SWIZZLE_128B((uint32_t)(row * 128 + colb));
                ldsm_x4(Bh2[nj][0], Bh2[nj][1], Bh2[nj][2], Bh2[nj][3], st + 32768 + off);
                ldsm_x4(Bl2[nj][0], Bl2[nj][1], Bl2[nj][2], Bl2[nj][3], st + 65536 + off);
            }

#pragma unroll
            for (int mi = 0; mi < 4; mi++) {
#pragma unroll
                for (int ni = 0; ni < 8; ni++) {
                    int half = ni >> 2;              // 0: rows 0-31, 1: rows 32-63
                    int nj = (ni >> 1) & 1;
                    int h = ni & 1;
                    uint32_t b0 = half ? Bh2[nj][h]     : Bh[nj][h];
                    uint32_t b1 = half ? Bh2[nj][2 + h] : Bh[nj][2 + h];
                    uint32_t c0 = half ? Bl2[nj][h]     : Bl[nj][h];
                    uint32_t c1 = half ? Bl2[nj][2 + h] : Bl[nj][2 + h];
                    float* d = acc[mi][ni];
                    mma16816(d, Ah[mi], b0, b1);   // hi*hi
                    mma16816(d, Ah[mi], c0, c1);   // hi*lo
                    mma16816(d, Al[mi], b0, b1);   // lo*hi
                }
            }
        }
    };

    // --- 2-stage pipeline ---
    load_chunk(0, 0);
    CP_COMMIT();
    for (int c = 0; c < nC; c++) {
        if (c + 1 < nC) {
            load_chunk(c + 1, (c + 1) & 1);
            CP_COMMIT();
            CP_WAIT_1();
        } else {
            CP_WAIT_0();
        }
        __syncthreads();
        compute_chunk(c & 1);
        __syncthreads();
    }

    // --- epilogue ---
    int gq = lane >> 2;          // 0..7  (row group)
    int t4 = lane & 3;           // 0..3  (column pair)
    float dinv = FINAL ? g_denom_inv[e] : 0.f;
    const int* sTok = (const int*)smem;

#pragma unroll
    for (int mi = 0; mi < 4; mi++) {
        int rA = wm + mi * 16 + gq;       // local row for d0,d1
        int rB = rA + 8;                  // local row for d2,d3
        int tok0 = 0, tok1 = 0;
        float sc0 = 0.f, sc1 = 0.f;
        if (FINAL) {
            tok0 = sTok[rA]; tok1 = sTok[rB];
            if (tok0 >= 0) sc0 = g_logit[tok0] * dinv;
            if (tok1 >= 0) sc1 = g_logit[tok1] * dinv;
        }
#pragma unroll
        for (int ni = 0; ni < 8; ni++) {
            int gcol = bn + wn + ni * 8 + t4 * 2;
            float2 bv = __ldg((const float2*)(bias + (size_t)e * NTOT + gcol));
            float* d = acc[mi][ni];
            if (FINAL) {
                if (tok0 >= 0) {
                    float2 v = make_float2(sc0 * (d[0] + bv.x), sc0 * (d[1] + bv.y));
                    *(float2*)(fout + (size_t)tok0 * DDIM + gcol) = v;
                }
                if (tok1 >= 0) {
                    float2 v = make_float2(sc1 * (d[2] + bv.x), sc1 * (d[3] + bv.y));
                    *(float2*)(fout + (size_t)tok1 * DDIM + gcol) = v;
                }
            } else {
                float f0 = d[0] + bv.x; f0 = f0 > 0.f ? f0 : 0.f;
                float f1 = d[1] + bv.y; f1 = f1 > 0.f ? f1 : 0.f;
                float f2 = d[2] + bv.x; f2 = f2 > 0.f ? f2 : 0.f;
                float f3 = d[3] + bv.y; f3 = f3 > 0.f ? f3 : 0.f;

                __nv_bfloat162 h01 = __float22bfloat162_rn(make_float2(f0, f1));
                __nv_bfloat162 h23 = __float22bfloat162_rn(make_float2(f2, f3));
                __nv_bfloat162 l01 = __float22bfloat162_rn(make_float2(
                    f0 - __bfloat162float(__low2bfloat16(h01)),
                    f1 - __bfloat162float(__high2bfloat16(h01))));
                __nv_bfloat162 l23 = __float22bfloat162_rn(make_float2(
                    f2 - __bfloat162float(__low2bfloat16(h23)),
                    f3 - __bfloat162float(__high2bfloat16(h23))));

                size_t oA = (size_t)(row0 + rA) * FDIM + gcol;
                size_t oB = (size_t)(row0 + rB) * FDIM + gcol;
                *(uint32_t*)(g_Hhi + oA) = *(uint32_t*)&h01;
                *(uint32_t*)(g_Hlo + oA) = *(uint32_t*)&l01;
                *(uint32_t*)(g_Hhi + oB) = *(uint32_t*)&h23;
                *(uint32_t*)(g_Hlo + oB) = *(uint32_t*)&l23;
            }
        }
    }
}

// ---------------------------------------------------------------------------
extern "C" void kernel_launch(void* const* d_in, const int* in_sizes, int n_in,
                              void* d_out, int out_size) {
    const float* x  = (const float*)d_in[0];   // [N, D]
    const float* Wg = (const float*)d_in[1];   // [E, D]
    const float* W1 = (const float*)d_in[2];   // [E, D, F]
    const float* b1 = (const float*)d_in[3];   // [E, F]
    const float* W2 = (const float*)d_in[4];   // [E, F, D]
    const float* b2 = (const float*)d_in[5];   // [E, D]
    float* out = (float*)d_out;                // [N, D]

    cudaFuncSetAttribute(moe_gemm_kernel<DDIM, false>,
                         cudaFuncAttributeMaxDynamicSharedMemorySize, SMEM_GEMM_BYTES);
    cudaFuncSetAttribute(moe_gemm_kernel<FDIM, true>,
                         cudaFuncAttributeMaxDynamicSharedMemorySize, SMEM_GEMM_BYTES);

    init_perm_kernel<<<PAD_ROWS / 256, 256>>>();
    router_kernel<<<N_TOK / 8, 256>>>(x, Wg);
    setup_kernel<<<1, 256>>>();
    scatter_kernel<<<N_TOK / 256, 256>>>();
    gather_x_kernel<<<PAD_ROWS, 128>>>(x);

    // W1 [E][D][F] -> W1T [E][F][D];  W2 [E][F][D] -> W2T [E][D][F]
    trans_conv_kernel<<<dim3(FDIM / 32, DDIM / 32, NEXP), 256>>>(W1, DDIM, FDIM, 0);
    trans_conv_kernel<<<dim3(DDIM / 32, FDIM / 32, NEXP), 256>>>(W2, FDIM, DDIM, 1);

    moe_gemm_kernel<DDIM, false><<<dim3(MAX_TILES, FDIM / 256), 256, SMEM_GEMM_BYTES>>>(b1, nullptr);
    moe_gemm_kernel<FDIM, true><<<dim3(MAX_TILES, DDIM / 256), 256, SMEM_GEMM_BYTES>>>(b2, out);
}

// round 6
// speedup vs baseline: 1.0135x; 1.0135x over previous
#include <cuda_runtime.h>
#include <cuda_bf16.h>
#include <cstdint>

// ---------------- problem constants ----------------
#define N_TOK  16384
#define DDIM   512
#define FDIM   2048
#define NEXP   8
#define CAP    16384.0f
#define EPSV   1e-6f

#define PAD_ROWS (N_TOK + NEXP * 128)   // 17408
#define MAX_TILES (PAD_ROWS / 128)      // 136

// ---------------- scratch (device globals; 16B-access aligned) ----------------
__device__ unsigned char g_expert[N_TOK];
__device__ float g_logit[N_TOK];
__device__ float g_denom_inv[NEXP];
__device__ int   g_off[NEXP + 1];
__device__ int   g_ctr[NEXP];
__device__ int   g_perm[PAD_ROWS];

__device__ __align__(256) __nv_bfloat16 g_Xhi[(size_t)PAD_ROWS * DDIM];
__device__ __align__(256) __nv_bfloat16 g_Xlo[(size_t)PAD_ROWS * DDIM];
__device__ __align__(256) __nv_bfloat16 g_Hhi[(size_t)PAD_ROWS * FDIM];
__device__ __align__(256) __nv_bfloat16 g_Hlo[(size_t)PAD_ROWS * FDIM];
__device__ __align__(256) __nv_bfloat16 g_W1Thi[(size_t)NEXP * FDIM * DDIM];  // [E][F][D]
__device__ __align__(256) __nv_bfloat16 g_W1Tlo[(size_t)NEXP * FDIM * DDIM];
__device__ __align__(256) __nv_bfloat16 g_W2Thi[(size_t)NEXP * DDIM * FDIM];  // [E][D][F]
__device__ __align__(256) __nv_bfloat16 g_W2Tlo[(size_t)NEXP * DDIM * FDIM];

// ---------------- helpers ----------------
__device__ __forceinline__ uint32_t smem_to_u32(const void* smem_ptr) {
    uint32_t addr;
    asm("{ .reg .u64 tmp; cvta.to.shared.u64 tmp, %1; cvt.u32.u64 %0, tmp; }"
        : "=r"(addr) : "l"(smem_ptr));
    return addr;
}

#define SMEM_SWIZZLE_128B(byte_offset) \
    ((byte_offset) ^ (((byte_offset) >> 3) & 0x70))

__device__ __forceinline__ void cp16(uint32_t dst, const void* src) {
    asm volatile("cp.async.cg.shared.global [%0], [%1], 16;"
                 :: "r"(dst), "l"(src) : "memory");
}
#define CP_COMMIT()  asm volatile("cp.async.commit_group;" ::: "memory")
#define CP_WAIT_1()  asm volatile("cp.async.wait_group 1;" ::: "memory")
#define CP_WAIT_0()  asm volatile("cp.async.wait_group 0;" ::: "memory")

__device__ __forceinline__ void ldsm_x4(uint32_t& r0, uint32_t& r1, uint32_t& r2,
                                        uint32_t& r3, uint32_t addr) {
    asm volatile("ldmatrix.sync.aligned.m8n8.x4.shared.b16 {%0,%1,%2,%3}, [%4];"
                 : "=r"(r0), "=r"(r1), "=r"(r2), "=r"(r3) : "r"(addr));
}
__device__ __forceinline__ void mma16816(float* d, const uint32_t* a,
                                         uint32_t b0, uint32_t b1) {
    asm volatile(
        "mma.sync.aligned.m16n8k16.row.col.f32.bf16.bf16.f32 "
        "{%0,%1,%2,%3},{%4,%5,%6,%7},{%8,%9},{%0,%1,%2,%3};"
        : "+f"(d[0]), "+f"(d[1]), "+f"(d[2]), "+f"(d[3])
        : "r"(a[0]), "r"(a[1]), "r"(a[2]), "r"(a[3]), "r"(b0), "r"(b1));
}

// ---------------------------------------------------------------------------
// 0) reset perm
// ---------------------------------------------------------------------------
__global__ void init_perm_kernel() {
    int i = blockIdx.x * blockDim.x + threadIdx.x;
    if (i < PAD_ROWS) g_perm[i] = -1;
}

// ---------------------------------------------------------------------------
// 1) router: logits = x @ Wg^T, top-1 per token (one warp per token)
// ---------------------------------------------------------------------------
__global__ __launch_bounds__(256) void router_kernel(const float* __restrict__ x,
                                                     const float* __restrict__ Wg) {
    __shared__ float sWg[NEXP * DDIM];
    int tid = threadIdx.x;
    for (int i = tid; i < NEXP * DDIM; i += 256) sWg[i] = Wg[i];
    __syncthreads();

    int warp = tid >> 5, lane = tid & 31;
    int token = blockIdx.x * 8 + warp;
    if (token >= N_TOK) return;

    const float* xr = x + (size_t)token * DDIM;
    float acc[NEXP];
#pragma unroll
    for (int e = 0; e < NEXP; e++) acc[e] = 0.f;
    for (int k = lane; k < DDIM; k += 32) {
        float xv = xr[k];
#pragma unroll
        for (int e = 0; e < NEXP; e++) acc[e] += xv * sWg[e * DDIM + k];
    }
#pragma unroll
    for (int e = 0; e < NEXP; e++) {
#pragma unroll
        for (int off = 16; off > 0; off >>= 1)
            acc[e] += __shfl_xor_sync(0xFFFFFFFF, acc[e], off);
    }
    if (lane == 0) {
        int best = 0;
#pragma unroll
        for (int e = 1; e < NEXP; e++)
            if (acc[e] > acc[best]) best = e;
        g_expert[token] = (unsigned char)best;
        g_logit[token]  = acc[best];
    }
}

// ---------------------------------------------------------------------------
// 2) setup (single block, deterministic tree reduction)
// ---------------------------------------------------------------------------
__global__ __launch_bounds__(256) void setup_kernel() {
    __shared__ float sden[NEXP][256];
    __shared__ int   scnt[NEXP][256];
    int tid = threadIdx.x;

    float den[NEXP]; int cnt[NEXP];
#pragma unroll
    for (int e = 0; e < NEXP; e++) { den[e] = 0.f; cnt[e] = 0; }
    for (int t = tid; t < N_TOK; t += 256) {
        int e = g_expert[t];
        den[e] += g_logit[t];
        cnt[e]++;
    }
#pragma unroll
    for (int e = 0; e < NEXP; e++) { sden[e][tid] = den[e]; scnt[e][tid] = cnt[e]; }
    __syncthreads();
    for (int s = 128; s > 0; s >>= 1) {
        if (tid < s) {
#pragma unroll
            for (int e = 0; e < NEXP; e++) {
                sden[e][tid] += sden[e][tid + s];
                scnt[e][tid] += scnt[e][tid + s];
            }
        }
        __syncthreads();
    }
    if (tid == 0) {
        int off = 0;
        for (int e = 0; e < NEXP; e++) {
            g_denom_inv[e] = CAP / (sden[e][0] + EPSV);
            g_off[e] = off;
            g_ctr[e] = off;
            off += ((scnt[e][0] + 127) >> 7) << 7;
        }
        g_off[NEXP] = off;
    }
}

// ---------------------------------------------------------------------------
// 3) scatter
// ---------------------------------------------------------------------------
__global__ void scatter_kernel() {
    int t = blockIdx.x * blockDim.x + threadIdx.x;
    if (t >= N_TOK) return;
    int e = g_expert[t];
    int pos = atomicAdd(&g_ctr[e], 1);
    g_perm[pos] = t;
}

// ---------------------------------------------------------------------------
// 4) gather x into sorted order + split to bf16 hi/lo
// ---------------------------------------------------------------------------
__global__ __launch_bounds__(128) void gather_x_kernel(const float* __restrict__ x) {
    int r = blockIdx.x;
    int t = threadIdx.x;
    int tok = g_perm[r];
    float4 v = make_float4(0.f, 0.f, 0.f, 0.f);
    if (tok >= 0) v = *(const float4*)(x + (size_t)tok * DDIM + t * 4);

    __nv_bfloat162 h0 = __float22bfloat162_rn(make_float2(v.x, v.y));
    __nv_bfloat162 h1 = __float22bfloat162_rn(make_float2(v.z, v.w));
    float2 l0f = make_float2(v.x - __bfloat162float(__low2bfloat16(h0)),
                             v.y - __bfloat162float(__high2bfloat16(h0)));
    float2 l1f = make_float2(v.z - __bfloat162float(__low2bfloat16(h1)),
                             v.w - __bfloat162float(__high2bfloat16(h1)));
    __nv_bfloat162 l0 = __float22bfloat162_rn(l0f);
    __nv_bfloat162 l1 = __float22bfloat162_rn(l1f);

    size_t off = (size_t)r * DDIM + t * 4;
    uint2 hh, ll;
    hh.x = *(uint32_t*)&h0; hh.y = *(uint32_t*)&h1;
    ll.x = *(uint32_t*)&l0; ll.y = *(uint32_t*)&l1;
    *(uint2*)(g_Xhi + off) = hh;
    *(uint2*)(g_Xlo + off) = ll;
}

// ---------------------------------------------------------------------------
// 5) transpose+split weights: in [E][R][C] fp32 -> out [E][C][R] bf16 hi/lo
// ---------------------------------------------------------------------------
__global__ __launch_bounds__(256) void trans_conv_kernel(const float* __restrict__ in,
                                                         int R, int C, int which) {
    __shared__ float tile[32][33];
    __nv_bfloat16* hiOut = which ? g_W2Thi : g_W1Thi;
    __nv_bfloat16* loOut = which ? g_W2Tlo : g_W1Tlo;

    int e  = blockIdx.z;
    int c0 = blockIdx.x * 32;
    int r0 = blockIdx.y * 32;
    int tx = threadIdx.x & 31;
    int ty8 = threadIdx.x >> 5;

    const float* src = in + ((size_t)e * R + r0) * C + c0;
#pragma unroll
    for (int i = 0; i < 32; i += 8)
        tile[ty8 + i][tx] = src[(size_t)(ty8 + i) * C + tx];
    __syncthreads();

    size_t ob = ((size_t)e * C + c0) * R + r0;
#pragma unroll
    for (int i = 0; i < 32; i += 8) {
        float f = tile[tx][ty8 + i];
        __nv_bfloat16 h = __float2bfloat16(f);
        __nv_bfloat16 l = __float2bfloat16(f - __bfloat162float(h));
        hiOut[ob + (size_t)(ty8 + i) * R + tx] = h;
        loOut[ob + (size_t)(ty8 + i) * R + tx] = l;
    }
}

// ---------------------------------------------------------------------------
// HMMA grouped GEMM:  C[128 x 256 tile] = A[128 x KTOT] @ B^T  (B: [N][K] K-major)
// bf16 3-pass split precision; cp.async 2-stage pipeline; ldmatrix + mma.sync.
// 8 warps, warp tile 64 x 64 (2 m-warps x 4 n-warps); B fragments staged in
// two 32-wide n-halves per k-step to cap register pressure (~200 regs).
//   FINAL=false: A = g_X (sorted), B = W1T, epilogue relu(+b1) -> g_H hi/lo
//   FINAL=true : A = g_H,          B = W2T, epilogue scale*(+b2) -> scatter to out
//
// smem per stage (96KB): Ahi 16K | Alo 16K | Bhi 32K | Blo 32K
// dynamic layout: [0,512) token ids (FINAL) | [1024 + p*98304) stages
// ---------------------------------------------------------------------------
#define STAGE_BYTES 98304
#define SMEM_GEMM_BYTES (1024 + 2 * STAGE_BYTES)   // 197632

template<int KTOT, bool FINAL>
__global__ __launch_bounds__(256, 1) void moe_gemm_kernel(
    const float* __restrict__ bias,   // [E][NTOT]
    float* __restrict__ fout)         // FINAL: [N_TOK][DDIM]
{
    constexpr int NTOT = FINAL ? DDIM : FDIM;
    extern __shared__ char smem[];
    uint32_t sbase = smem_to_u32(smem);
    int tid = threadIdx.x;
    int lane = tid & 31, wid = tid >> 5;

    int row0 = blockIdx.x * 128;
    int total = g_off[NEXP];
    if (row0 >= total) return;
    int e = 0;
    while (g_off[e + 1] <= row0) e++;
    int bn = blockIdx.y * 256;

    if (FINAL && tid < 128) ((int*)smem)[tid] = g_perm[row0 + tid];

    const __nv_bfloat16* Ahi = (FINAL ? g_Hhi : g_Xhi) + (size_t)row0 * KTOT;
    const __nv_bfloat16* Alo = (FINAL ? g_Hlo : g_Xlo) + (size_t)row0 * KTOT;
    const __nv_bfloat16* Bhi = (FINAL ? g_W2Thi : g_W1Thi) + ((size_t)e * NTOT + bn) * KTOT;
    const __nv_bfloat16* Blo = (FINAL ? g_W2Tlo : g_W1Tlo) + ((size_t)e * NTOT + bn) * KTOT;

    const int nC = KTOT / 64;

    // warp tile: 64 (m) x 64 (n); warps laid out 2 (m) x 4 (n)
    int wm = (wid & 1) * 64;
    int wn = (wid >> 1) * 64;

    float acc[4][8][4];
#pragma unroll
    for (int mi = 0; mi < 4; mi++)
#pragma unroll
        for (int ni = 0; ni < 8; ni++)
#pragma unroll
            for (int q = 0; q < 4; q++) acc[mi][ni][q] = 0.f;

    // --- async load of one 64-wide K chunk into stage p ---
    auto load_chunk = [&](int c, int p) {
        int kt = c * 64;
        uint32_t base = sbase + 1024 + p * STAGE_BYTES;
        // A: 128 rows -> 1024 16B units per array
#pragma unroll
        for (int i = 0; i < 4; i++) {
            int u = tid + i * 256;
            int r = u >> 3, s = u & 7;
            uint32_t sw = SMEM_SWIZZLE_128B((uint32_t)(r * 128 + s * 16));
            size_t goff = (size_t)r * KTOT + kt + s * 8;
            cp16(base +         sw, Ahi + goff);
            cp16(base + 16384 + sw, Alo + goff);
        }
        // B: 256 rows -> 2048 16B units per array
#pragma unroll
        for (int i = 0; i < 8; i++) {
            int u = tid + i * 256;
            int r = u >> 3, s = u & 7;
            uint32_t sw = SMEM_SWIZZLE_128B((uint32_t)(r * 128 + s * 16));
            size_t goff = (size_t)r * KTOT + kt + s * 8;
            cp16(base + 32768 + sw, Bhi + goff);
            cp16(base + 65536 + sw, Blo + goff);
        }
    };

    // --- compute one staged chunk (4 k-steps of 16) ---
    auto compute_chunk = [&](int p) {
        uint32_t st = sbase + 1024 + p * STAGE_BYTES;
#pragma unroll
        for (int ks = 0; ks < 4; ks++) {
            int k0 = ks * 16;
            int colb = (k0 + (lane >> 4) * 8) * 2;

            uint32_t Ah[4][4], Al[4][4];
#pragma unroll
            for (int mi = 0; mi < 4; mi++) {
                int row = wm + mi * 16 + (lane & 15);
                uint32_t off = SMEM_SWIZZLE_128B((uint32_t)(row * 128 + colb));
                ldsm_x4(Ah[mi][0], Ah[mi][1], Ah[mi][2], Ah[mi][3], st + off);
                ldsm_x4(Al[mi][0], Al[mi][1], Al[mi][2], Al[mi][3], st + 16384 + off);
            }
            // two 32-wide n-halves; only 16 B regs live at once
#pragma unroll
            for (int bh = 0; bh < 2; bh++) {
                uint32_t Bh[2][4], Bl[2][4];
#pragma unroll
                for (int nj = 0; nj < 2; nj++) {
                    int row = wn + bh * 32 + nj * 16 + (lane & 15);
                    uint32_t off = SMEM_SWIZZLE_128B((uint32_t)(row * 128 + colb));
                    ldsm_x4(Bh[nj][0], Bh[nj][1], Bh[nj][2], Bh[nj][3], st + 32768 + off);
                    ldsm_x4(Bl[nj][0], Bl[nj][1], Bl[nj][2], Bl[nj][3], st + 65536 + off);
                }
#pragma unroll
                for (int mi = 0; mi < 4; mi++) {
#pragma unroll
                    for (int nq = 0; nq < 4; nq++) {
                        int nj = nq >> 1;
                        int h = nq & 1;
                        // x4 at 16 rows: m0=rows0-7@k0, m1=rows8-15@k0,
                        //                m2=rows0-7@k0+8, m3=rows8-15@k0+8
                        uint32_t b0 = Bh[nj][h], b1 = Bh[nj][2 + h];
                        uint32_t c0 = Bl[nj][h], c1 = Bl[nj][2 + h];
                        float* d = acc[mi][bh * 4 + nq];
                        mma16816(d, Ah[mi], b0, b1);   // hi*hi
                        mma16816(d, Ah[mi], c0, c1);   // hi*lo
                        mma16816(d, Al[mi], b0, b1);   // lo*hi
                    }
                }
            }
        }
    };

    // --- 2-stage pipeline ---
    load_chunk(0, 0);
    CP_COMMIT();
    for (int c = 0; c < nC; c++) {
        if (c + 1 < nC) {
            load_chunk(c + 1, (c + 1) & 1);
            CP_COMMIT();
            CP_WAIT_1();
        } else {
            CP_WAIT_0();
        }
        __syncthreads();
        compute_chunk(c & 1);
        __syncthreads();
    }

    // --- epilogue ---
    int gq = lane >> 2;          // 0..7  (row group)
    int t4 = lane & 3;           // 0..3  (column pair)
    float dinv = FINAL ? g_denom_inv[e] : 0.f;
    const int* sTok = (const int*)smem;

#pragma unroll
    for (int mi = 0; mi < 4; mi++) {
        int rA = wm + mi * 16 + gq;       // local row for d0,d1
        int rB = rA + 8;                  // local row for d2,d3
        int tok0 = 0, tok1 = 0;
        float sc0 = 0.f, sc1 = 0.f;
        if (FINAL) {
            tok0 = sTok[rA]; tok1 = sTok[rB];
            if (tok0 >= 0) sc0 = g_logit[tok0] * dinv;
            if (tok1 >= 0) sc1 = g_logit[tok1] * dinv;
        }
#pragma unroll
        for (int ni = 0; ni < 8; ni++) {
            int gcol = bn + wn + ni * 8 + t4 * 2;
            float2 bv = __ldg((const float2*)(bias + (size_t)e * NTOT + gcol));
            float* d = acc[mi][ni];
            if (FINAL) {
                if (tok0 >= 0) {
                    float2 v = make_float2(sc0 * (d[0] + bv.x), sc0 * (d[1] + bv.y));
                    *(float2*)(fout + (size_t)tok0 * DDIM + gcol) = v;
                }
                if (tok1 >= 0) {
                    float2 v = make_float2(sc1 * (d[2] + bv.x), sc1 * (d[3] + bv.y));
                    *(float2*)(fout + (size_t)tok1 * DDIM + gcol) = v;
                }
            } else {
                float f0 = d[0] + bv.x; f0 = f0 > 0.f ? f0 : 0.f;
                float f1 = d[1] + bv.y; f1 = f1 > 0.f ? f1 : 0.f;
                float f2 = d[2] + bv.x; f2 = f2 > 0.f ? f2 : 0.f;
                float f3 = d[3] + bv.y; f3 = f3 > 0.f ? f3 : 0.f;

                __nv_bfloat162 h01 = __float22bfloat162_rn(make_float2(f0, f1));
                __nv_bfloat162 h23 = __float22bfloat162_rn(make_float2(f2, f3));
                __nv_bfloat162 l01 = __float22bfloat162_rn(make_float2(
                    f0 - __bfloat162float(__low2bfloat16(h01)),
                    f1 - __bfloat162float(__high2bfloat16(h01))));
                __nv_bfloat162 l23 = __float22bfloat162_rn(make_float2(
                    f2 - __bfloat162float(__low2bfloat16(h23)),
                    f3 - __bfloat162float(__high2bfloat16(h23))));

                size_t oA = (size_t)(row0 + rA) * FDIM + gcol;
                size_t oB = (size_t)(row0 + rB) * FDIM + gcol;
                *(uint32_t*)(g_Hhi + oA) = *(uint32_t*)&h01;
                *(uint32_t*)(g_Hlo + oA) = *(uint32_t*)&l01;
                *(uint32_t*)(g_Hhi + oB) = *(uint32_t*)&h23;
                *(uint32_t*)(g_Hlo + oB) = *(uint32_t*)&l23;
            }
        }
    }
}

// ---------------------------------------------------------------------------
extern "C" void kernel_launch(void* const* d_in, const int* in_sizes, int n_in,
                              void* d_out, int out_size) {
    const float* x  = (const float*)d_in[0];   // [N, D]
    const float* Wg = (const float*)d_in[1];   // [E, D]
    const float* W1 = (const float*)d_in[2];   // [E, D, F]
    const float* b1 = (const float*)d_in[3];   // [E, F]
    const float* W2 = (const float*)d_in[4];   // [E, F, D]
    const float* b2 = (const float*)d_in[5];   // [E, D]
    float* out = (float*)d_out;                // [N, D]

    cudaFuncSetAttribute(moe_gemm_kernel<DDIM, false>,
                         cudaFuncAttributeMaxDynamicSharedMemorySize, SMEM_GEMM_BYTES);
    cudaFuncSetAttribute(moe_gemm_kernel<FDIM, true>,
                         cudaFuncAttributeMaxDynamicSharedMemorySize, SMEM_GEMM_BYTES);

    init_perm_kernel<<<PAD_ROWS / 256, 256>>>();
    router_kernel<<<N_TOK / 8, 256>>>(x, Wg);
    setup_kernel<<<1, 256>>>();
    scatter_kernel<<<N_TOK / 256, 256>>>();
    gather_x_kernel<<<PAD_ROWS, 128>>>(x);

    // W1 [E][D][F] -> W1T [E][F][D];  W2 [E][F][D] -> W2T [E][D][F]
    trans_conv_kernel<<<dim3(FDIM / 32, DDIM / 32, NEXP), 256>>>(W1, DDIM, FDIM, 0);
    trans_conv_kernel<<<dim3(DDIM / 32, FDIM / 32, NEXP), 256>>>(W2, FDIM, DDIM, 1);

    moe_gemm_kernel<DDIM, false><<<dim3(MAX_TILES, FDIM / 256), 256, SMEM_GEMM_BYTES>>>(b1, nullptr);
    moe_gemm_kernel<FDIM, true><<<dim3(MAX_TILES, DDIM / 256), 256, SMEM_GEMM_BYTES>>>(b2, out);
}

// round 8
// speedup vs baseline: 1.1320x; 1.1169x over previous
#include <cuda_runtime.h>
#include <cuda_bf16.h>
#include <cstdint>

// ---------------- problem constants ----------------
#define N_TOK  16384
#define DDIM   512
#define FDIM   2048
#define NEXP   8
#define CAP    16384.0f
#define EPSV   1e-6f

#define PAD_ROWS (N_TOK + NEXP * 128)   // 17408
#define MAX_TILES (PAD_ROWS / 128)      // 136

// ---------------- scratch (device globals; 16B-access aligned) ----------------
__device__ unsigned char g_expert[N_TOK];
__device__ float g_logit[N_TOK];
__device__ float g_denom_inv[NEXP];
__device__ int   g_off[NEXP + 1];
__device__ int   g_ctr[NEXP];
__device__ int   g_perm[PAD_ROWS];

__device__ __align__(256) __nv_bfloat16 g_Xhi[(size_t)PAD_ROWS * DDIM];
__device__ __align__(256) __nv_bfloat16 g_Xlo[(size_t)PAD_ROWS * DDIM];
__device__ __align__(256) __nv_bfloat16 g_Hhi[(size_t)PAD_ROWS * FDIM];
__device__ __align__(256) __nv_bfloat16 g_Hlo[(size_t)PAD_ROWS * FDIM];
__device__ __align__(256) __nv_bfloat16 g_W1Thi[(size_t)NEXP * FDIM * DDIM];  // [E][F][D]
__device__ __align__(256) __nv_bfloat16 g_W1Tlo[(size_t)NEXP * FDIM * DDIM];
__device__ __align__(256) __nv_bfloat16 g_W2Thi[(size_t)NEXP * DDIM * FDIM];  // [E][D][F]
__device__ __align__(256) __nv_bfloat16 g_W2Tlo[(size_t)NEXP * DDIM * FDIM];

// ---------------- helpers ----------------
__device__ __forceinline__ uint32_t smem_to_u32(const void* smem_ptr) {
    uint32_t addr;
    asm("{ .reg .u64 tmp; cvta.to.shared.u64 tmp, %1; cvt.u32.u64 %0, tmp; }"
        : "=r"(addr) : "l"(smem_ptr));
    return addr;
}

#define SMEM_SWIZZLE_128B(byte_offset) \
    ((byte_offset) ^ (((byte_offset) >> 3) & 0x70))

__device__ __forceinline__ void cp16(uint32_t dst, const void* src) {
    asm volatile("cp.async.cg.shared.global [%0], [%1], 16;"
                 :: "r"(dst), "l"(src) : "memory");
}
#define CP_COMMIT()  asm volatile("cp.async.commit_group;" ::: "memory")
#define CP_WAIT_1()  asm volatile("cp.async.wait_group 1;" ::: "memory")
#define CP_WAIT_0()  asm volatile("cp.async.wait_group 0;" ::: "memory")

__device__ __forceinline__ void ldsm_x4(uint32_t& r0, uint32_t& r1, uint32_t& r2,
                                        uint32_t& r3, uint32_t addr) {
    asm volatile("ldmatrix.sync.aligned.m8n8.x4.shared.b16 {%0,%1,%2,%3}, [%4];"
                 : "=r"(r0), "=r"(r1), "=r"(r2), "=r"(r3) : "r"(addr));
}
__device__ __forceinline__ void ldsm_x2(uint32_t& r0, uint32_t& r1, uint32_t addr) {
    asm volatile("ldmatrix.sync.aligned.m8n8.x2.shared.b16 {%0,%1}, [%2];"
                 : "=r"(r0), "=r"(r1) : "r"(addr));
}
__device__ __forceinline__ void mma16816(float* d, const uint32_t* a,
                                         uint32_t b0, uint32_t b1) {
    asm volatile(
        "mma.sync.aligned.m16n8k16.row.col.f32.bf16.bf16.f32 "
        "{%0,%1,%2,%3},{%4,%5,%6,%7},{%8,%9},{%0,%1,%2,%3};"
        : "+f"(d[0]), "+f"(d[1]), "+f"(d[2]), "+f"(d[3])
        : "r"(a[0]), "r"(a[1]), "r"(a[2]), "r"(a[3]), "r"(b0), "r"(b1));
}

// ---------------------------------------------------------------------------
// 0) reset perm
// ---------------------------------------------------------------------------
__global__ void init_perm_kernel() {
    int i = blockIdx.x * blockDim.x + threadIdx.x;
    if (i < PAD_ROWS) g_perm[i] = -1;
}

// ---------------------------------------------------------------------------
// 1) router: logits = x @ Wg^T, top-1 per token (one warp per token)
// ---------------------------------------------------------------------------
__global__ __launch_bounds__(256) void router_kernel(const float* __restrict__ x,
                                                     const float* __restrict__ Wg) {
    __shared__ float sWg[NEXP * DDIM];
    int tid = threadIdx.x;
    for (int i = tid; i < NEXP * DDIM; i += 256) sWg[i] = Wg[i];
    __syncthreads();

    int warp = tid >> 5, lane = tid & 31;
    int token = blockIdx.x * 8 + warp;
    if (token >= N_TOK) return;

    const float* xr = x + (size_t)token * DDIM;
    float acc[NEXP];
#pragma unroll
    for (int e = 0; e < NEXP; e++) acc[e] = 0.f;
    for (int k = lane; k < DDIM; k += 32) {
        float xv = xr[k];
#pragma unroll
        for (int e = 0; e < NEXP; e++) acc[e] += xv * sWg[e * DDIM + k];
    }
#pragma unroll
    for (int e = 0; e < NEXP; e++) {
#pragma unroll
        for (int off = 16; off > 0; off >>= 1)
            acc[e] += __shfl_xor_sync(0xFFFFFFFF, acc[e], off);
    }
    if (lane == 0) {
        int best = 0;
#pragma unroll
        for (int e = 1; e < NEXP; e++)
            if (acc[e] > acc[best]) best = e;
        g_expert[token] = (unsigned char)best;
        g_logit[token]  = acc[best];
    }
}

// ---------------------------------------------------------------------------
// 2) setup (single block, deterministic tree reduction)
// ---------------------------------------------------------------------------
__global__ __launch_bounds__(256) void setup_kernel() {
    __shared__ float sden[NEXP][256];
    __shared__ int   scnt[NEXP][256];
    int tid = threadIdx.x;

    float den[NEXP]; int cnt[NEXP];
#pragma unroll
    for (int e = 0; e < NEXP; e++) { den[e] = 0.f; cnt[e] = 0; }
    for (int t = tid; t < N_TOK; t += 256) {
        int e = g_expert[t];
        den[e] += g_logit[t];
        cnt[e]++;
    }
#pragma unroll
    for (int e = 0; e < NEXP; e++) { sden[e][tid] = den[e]; scnt[e][tid] = cnt[e]; }
    __syncthreads();
    for (int s = 128; s > 0; s >>= 1) {
        if (tid < s) {
#pragma unroll
            for (int e = 0; e < NEXP; e++) {
                sden[e][tid] += sden[e][tid + s];
                scnt[e][tid] += scnt[e][tid + s];
            }
        }
        __syncthreads();
    }
    if (tid == 0) {
        int off = 0;
        for (int e = 0; e < NEXP; e++) {
            g_denom_inv[e] = CAP / (sden[e][0] + EPSV);
            g_off[e] = off;
            g_ctr[e] = off;
            off += ((scnt[e][0] + 127) >> 7) << 7;
        }
        g_off[NEXP] = off;
    }
}

// ---------------------------------------------------------------------------
// 3) scatter
// ---------------------------------------------------------------------------
__global__ void scatter_kernel() {
    int t = blockIdx.x * blockDim.x + threadIdx.x;
    if (t >= N_TOK) return;
    int e = g_expert[t];
    int pos = atomicAdd(&g_ctr[e], 1);
    g_perm[pos] = t;
}

// ---------------------------------------------------------------------------
// 4) gather x into sorted order + split to bf16 hi/lo
// ---------------------------------------------------------------------------
__global__ __launch_bounds__(128) void gather_x_kernel(const float* __restrict__ x) {
    int r = blockIdx.x;
    int t = threadIdx.x;
    int tok = g_perm[r];
    float4 v = make_float4(0.f, 0.f, 0.f, 0.f);
    if (tok >= 0) v = *(const float4*)(x + (size_t)tok * DDIM + t * 4);

    __nv_bfloat162 h0 = __float22bfloat162_rn(make_float2(v.x, v.y));
    __nv_bfloat162 h1 = __float22bfloat162_rn(make_float2(v.z, v.w));
    float2 l0f = make_float2(v.x - __bfloat162float(__low2bfloat16(h0)),
                             v.y - __bfloat162float(__high2bfloat16(h0)));
    float2 l1f = make_float2(v.z - __bfloat162float(__low2bfloat16(h1)),
                             v.w - __bfloat162float(__high2bfloat16(h1)));
    __nv_bfloat162 l0 = __float22bfloat162_rn(l0f);
    __nv_bfloat162 l1 = __float22bfloat162_rn(l1f);

    size_t off = (size_t)r * DDIM + t * 4;
    uint2 hh, ll;
    hh.x = *(uint32_t*)&h0; hh.y = *(uint32_t*)&h1;
    ll.x = *(uint32_t*)&l0; ll.y = *(uint32_t*)&l1;
    *(uint2*)(g_Xhi + off) = hh;
    *(uint2*)(g_Xlo + off) = ll;
}

// ---------------------------------------------------------------------------
// 5) transpose+split weights: in [E][R][C] fp32 -> out [E][C][R] bf16 hi/lo
// ---------------------------------------------------------------------------
__global__ __launch_bounds__(256) void trans_conv_kernel(const float* __restrict__ in,
                                                         int R, int C, int which) {
    __shared__ float tile[32][33];
    __nv_bfloat16* hiOut = which ? g_W2Thi : g_W1Thi;
    __nv_bfloat16* loOut = which ? g_W2Tlo : g_W1Tlo;

    int e  = blockIdx.z;
    int c0 = blockIdx.x * 32;
    int r0 = blockIdx.y * 32;
    int tx = threadIdx.x & 31;
    int ty8 = threadIdx.x >> 5;

    const float* src = in + ((size_t)e * R + r0) * C + c0;
#pragma unroll
    for (int i = 0; i < 32; i += 8)
        tile[ty8 + i][tx] = src[(size_t)(ty8 + i) * C + tx];
    __syncthreads();

    size_t ob = ((size_t)e * C + c0) * R + r0;
#pragma unroll
    for (int i = 0; i < 32; i += 8) {
        float f = tile[tx][ty8 + i];
        __nv_bfloat16 h = __float2bfloat16(f);
        __nv_bfloat16 l = __float2bfloat16(f - __bfloat162float(h));
        hiOut[ob + (size_t)(ty8 + i) * R + tx] = h;
        loOut[ob + (size_t)(ty8 + i) * R + tx] = l;
    }
}

// ---------------------------------------------------------------------------
// HMMA grouped GEMM (R4 geometry):
//   C[128 x 128 tile] = A[128 x KTOT] @ B^T  (B: [N][K] K-major)
// bf16 3-pass split precision; cp.async 3-STAGE pipeline, ONE sync per chunk;
// ldmatrix + mma.sync; 8 warps, warp tile 64 x 32 (2 m-warps x 4 n-warps);
// MMA emission pass-outermost to break accumulator RAW chains.
//   FINAL=false: A = g_X (sorted), B = W1T, epilogue relu(+b1) -> g_H hi/lo
//   FINAL=true : A = g_H,          B = W2T, epilogue scale*(+b2) -> scatter to out
//
// smem per stage (64KB): Ahi 16K | Alo 16K | Bhi 16K | Blo 16K
// dynamic layout: [0,512) token ids (FINAL) | [1024 + p*65536) stages (3)
// ---------------------------------------------------------------------------
#define STAGE_BYTES 65536
#define SMEM_GEMM_BYTES (1024 + 3 * STAGE_BYTES)   // 197632

template<int KTOT, bool FINAL>
__global__ __launch_bounds__(256, 1) void moe_gemm_kernel(
    const float* __restrict__ bias,   // [E][NTOT]
    float* __restrict__ fout)         // FINAL: [N_TOK][DDIM]
{
    constexpr int NTOT = FINAL ? DDIM : FDIM;
    extern __shared__ char smem[];
    uint32_t sbase = smem_to_u32(smem);
    int tid = threadIdx.x;
    int lane = tid & 31, wid = tid >> 5;

    int row0 = blockIdx.x * 128;
    int total = g_off[NEXP];
    if (row0 >= total) return;
    int e = 0;
    while (g_off[e + 1] <= row0) e++;
    int bn = blockIdx.y * 128;

    if (FINAL && tid < 128) ((int*)smem)[tid] = g_perm[row0 + tid];

    const __nv_bfloat16* Ahi = (FINAL ? g_Hhi : g_Xhi) + (size_t)row0 * KTOT;
    const __nv_bfloat16* Alo = (FINAL ? g_Hlo : g_Xlo) + (size_t)row0 * KTOT;
    const __nv_bfloat16* Bhi = (FINAL ? g_W2Thi : g_W1Thi) + ((size_t)e * NTOT + bn) * KTOT;
    const __nv_bfloat16* Blo = (FINAL ? g_W2Tlo : g_W1Tlo) + ((size_t)e * NTOT + bn) * KTOT;

    const int nC = KTOT / 64;

    // warp tile: 64 (m) x 32 (n); warps laid out 2 (m) x 4 (n)
    int wm = (wid & 1) * 64;
    int wn = (wid >> 1) * 32;

    float acc[4][4][4];
#pragma unroll
    for (int mi = 0; mi < 4; mi++)
#pragma unroll
        for (int ni = 0; ni < 4; ni++)
#pragma unroll
            for (int q = 0; q < 4; q++) acc[mi][ni][q] = 0.f;

    // --- async load of one 64-wide K chunk into stage p ---
    auto load_chunk = [&](int c, int p) {
        int kt = c * 64;
        uint32_t base = sbase + 1024 + p * STAGE_BYTES;
#pragma unroll
        for (int i = 0; i < 4; i++) {
            int u = tid + i * 256;          // 0..1023
            int r = u >> 3, s = u & 7;      // row, 16B-chunk
            uint32_t sw = SMEM_SWIZZLE_128B((uint32_t)(r * 128 + s * 16));
            size_t goff = (size_t)r * KTOT + kt + s * 8;
            cp16(base +         sw, Ahi + goff);
            cp16(base + 16384 + sw, Alo + goff);
            cp16(base + 32768 + sw, Bhi + goff);
            cp16(base + 49152 + sw, Blo + goff);
        }
    };

    // --- compute one staged chunk (4 k-steps of 16) ---
    auto compute_chunk = [&](int p) {
        uint32_t aHiB = sbase + 1024 + p * STAGE_BYTES;
        uint32_t aLoB = aHiB + 16384;
        uint32_t bHiB = aHiB + 32768;
        uint32_t bLoB = aHiB + 49152;
#pragma unroll
        for (int ks = 0; ks < 4; ks++) {
            int k0 = ks * 16;
            uint32_t Ah[4][4], Al[4][4];
#pragma unroll
            for (int mi = 0; mi < 4; mi++) {
                int row = wm + mi * 16 + (lane & 15);
                int colb = (k0 + (lane >> 4) * 8) * 2;
                uint32_t off = SMEM_SWIZZLE_128B((uint32_t)(row * 128 + colb));
                ldsm_x4(Ah[mi][0], Ah[mi][1], Ah[mi][2], Ah[mi][3], aHiB + off);
                ldsm_x4(Al[mi][0], Al[mi][1], Al[mi][2], Al[mi][3], aLoB + off);
            }
            uint32_t Bh[4][2], Bl[4][2];
#pragma unroll
            for (int ni = 0; ni < 4; ni++) {
                int row = wn + ni * 8 + (lane & 7);
                int colb = (k0 + ((lane >> 3) & 1) * 8) * 2;
                uint32_t off = SMEM_SWIZZLE_128B((uint32_t)(row * 128 + colb));
                ldsm_x2(Bh[ni][0], Bh[ni][1], bHiB + off);
                ldsm_x2(Bl[ni][0], Bl[ni][1], bLoB + off);
            }
            // pass-outermost: 16 independent MMAs between same-acc touches
#pragma unroll
            for (int mi = 0; mi < 4; mi++)
#pragma unroll
                for (int ni = 0; ni < 4; ni++)
                    mma16816(acc[mi][ni], Ah[mi], Bh[ni][0], Bh[ni][1]);  // hi*hi
#pragma unroll
            for (int mi = 0; mi < 4; mi++)
#pragma unroll
                for (int ni = 0; ni < 4; ni++)
                    mma16816(acc[mi][ni], Ah[mi], Bl[ni][0], Bl[ni][1]);  // hi*lo
#pragma unroll
            for (int mi = 0; mi < 4; mi++)
#pragma unroll
                for (int ni = 0; ni < 4; ni++)
                    mma16816(acc[mi][ni], Al[mi], Bh[ni][0], Bh[ni][1]);  // lo*hi
        }
    };

    // --- 3-stage pipeline, one __syncthreads per chunk ---
    load_chunk(0, 0);
    CP_COMMIT();
    if (nC > 1) { load_chunk(1, 1); CP_COMMIT(); }
    for (int c = 0; c < nC; c++) {
        if (c + 1 < nC) CP_WAIT_1(); else CP_WAIT_0();
        __syncthreads();
        if (c + 2 < nC) { load_chunk(c + 2, (c + 2) % 3); CP_COMMIT(); }
        compute_chunk(c % 3);
    }

    // --- epilogue ---
    int gq = lane >> 2;          // 0..7  (row group)
    int t4 = lane & 3;           // 0..3  (column pair)
    float dinv = FINAL ? g_denom_inv[e] : 0.f;
    const int* sTok = (const int*)smem;

#pragma unroll
    for (int mi = 0; mi < 4; mi++) {
        int rA = wm + mi * 16 + gq;       // local row for d0,d1
        int rB = rA + 8;                  // local row for d2,d3
        int tok0 = 0, tok1 = 0;
        float sc0 = 0.f, sc1 = 0.f;
        if (FINAL) {
            tok0 = sTok[rA]; tok1 = sTok[rB];
            if (tok0 >= 0) sc0 = g_logit[tok0] * dinv;
            if (tok1 >= 0) sc1 = g_logit[tok1] * dinv;
        }
#pragma unroll
        for (int ni = 0; ni < 4; ni++) {
            int gcol = bn + wn + ni * 8 + t4 * 2;
            float2 bv = __ldg((const float2*)(bias + (size_t)e * NTOT + gcol));
            float* d = acc[mi][ni];
            if (FINAL) {
                if (tok0 >= 0) {
                    float2 v = make_float2(sc0 * (d[0] + bv.x), sc0 * (d[1] + bv.y));
                    *(float2*)(fout + (size_t)tok0 * DDIM + gcol) = v;
                }
                if (tok1 >= 0) {
                    float2 v = make_float2(sc1 * (d[2] + bv.x), sc1 * (d[3] + bv.y));
                    *(float2*)(fout + (size_t)tok1 * DDIM + gcol) = v;
                }
            } else {
                float f0 = d[0] + bv.x; f0 = f0 > 0.f ? f0 : 0.f;
                float f1 = d[1] + bv.y; f1 = f1 > 0.f ? f1 : 0.f;
                float f2 = d[2] + bv.x; f2 = f2 > 0.f ? f2 : 0.f;
                float f3 = d[3] + bv.y; f3 = f3 > 0.f ? f3 : 0.f;

                __nv_bfloat162 h01 = __float22bfloat162_rn(make_float2(f0, f1));
                __nv_bfloat162 h23 = __float22bfloat162_rn(make_float2(f2, f3));
                __nv_bfloat162 l01 = __float22bfloat162_rn(make_float2(
                    f0 - __bfloat162float(__low2bfloat16(h01)),
                    f1 - __bfloat162float(__high2bfloat16(h01))));
                __nv_bfloat162 l23 = __float22bfloat162_rn(make_float2(
                    f2 - __bfloat162float(__low2bfloat16(h23)),
                    f3 - __bfloat162float(__high2bfloat16(h23))));

                size_t oA = (size_t)(row0 + rA) * FDIM + gcol;
                size_t oB = (size_t)(row0 + rB) * FDIM + gcol;
                *(uint32_t*)(g_Hhi + oA) = *(uint32_t*)&h01;
                *(uint32_t*)(g_Hlo + oA) = *(uint32_t*)&l01;
                *(uint32_t*)(g_Hhi + oB) = *(uint32_t*)&h23;
                *(uint32_t*)(g_Hlo + oB) = *(uint32_t*)&l23;
            }
        }
    }
}

// ---------------------------------------------------------------------------
extern "C" void kernel_launch(void* const* d_in, const int* in_sizes, int n_in,
                              void* d_out, int out_size) {
    const float* x  = (const float*)d_in[0];   // [N, D]
    const float* Wg = (const float*)d_in[1];   // [E, D]
    const float* W1 = (const float*)d_in[2];   // [E, D, F]
    const float* b1 = (const float*)d_in[3];   // [E, F]
    const float* W2 = (const float*)d_in[4];   // [E, F, D]
    const float* b2 = (const float*)d_in[5];   // [E, D]
    float* out = (float*)d_out;                // [N, D]

    cudaFuncSetAttribute(moe_gemm_kernel<DDIM, false>,
                         cudaFuncAttributeMaxDynamicSharedMemorySize, SMEM_GEMM_BYTES);
    cudaFuncSetAttribute(moe_gemm_kernel<FDIM, true>,
                         cudaFuncAttributeMaxDynamicSharedMemorySize, SMEM_GEMM_BYTES);

    init_perm_kernel<<<PAD_ROWS / 256, 256>>>();
    router_kernel<<<N_TOK / 8, 256>>>(x, Wg);
    setup_kernel<<<1, 256>>>();
    scatter_kernel<<<N_TOK / 256, 256>>>();
    gather_x_kernel<<<PAD_ROWS, 128>>>(x);

    // W1 [E][D][F] -> W1T [E][F][D];  W2 [E][F][D] -> W2T [E][D][F]
    trans_conv_kernel<<<dim3(FDIM / 32, DDIM / 32, NEXP), 256>>>(W1, DDIM, FDIM, 0);
    trans_conv_kernel<<<dim3(DDIM / 32, FDIM / 32, NEXP), 256>>>(W2, FDIM, DDIM, 1);

    moe_gemm_kernel<DDIM, false><<<dim3(MAX_TILES, FDIM / 128), 256, SMEM_GEMM_BYTES>>>(b1, nullptr);
    moe_gemm_kernel<FDIM, true><<<dim3(MAX_TILES, DDIM / 128), 256, SMEM_GEMM_BYTES>>>(b2, out);
}

// round 11
// speedup vs baseline: 1.5116x; 1.3352x over previous
#include <cuda_runtime.h>
#include <cuda_fp16.h>
#include <cstdint>

// ---------------- problem constants ----------------
#define N_TOK  16384
#define DDIM   512
#define FDIM   2048
#define NEXP   8
#define CAP    16384.0f
#define EPSV   1e-6f

#define PAD_ROWS (N_TOK + NEXP * 128)   // 17408
#define MAX_TILES (PAD_ROWS / 128)      // 136

// ---------------- scratch (device globals; 16B-access aligned) ----------------
__device__ unsigned char g_expert[N_TOK];
__device__ float g_logit[N_TOK];
__device__ float g_denom_inv[NEXP];
__device__ int   g_off[NEXP + 1];
__device__ int   g_ctr[NEXP];
__device__ int   g_perm[PAD_ROWS];

__device__ __align__(256) __half g_X[(size_t)PAD_ROWS * DDIM];     // gathered x, fp16
__device__ __align__(256) __half g_H[(size_t)PAD_ROWS * FDIM];     // hidden, fp16
__device__ __align__(256) __half g_W1Thi[(size_t)NEXP * FDIM * DDIM];  // [E][F][D]
__device__ __align__(256) __half g_W1Tlo[(size_t)NEXP * FDIM * DDIM];
__device__ __align__(256) __half g_W2Thi[(size_t)NEXP * DDIM * FDIM];  // [E][D][F]
__device__ __align__(256) __half g_W2Tlo[(size_t)NEXP * DDIM * FDIM];

// ---------------- helpers ----------------
__device__ __forceinline__ uint32_t smem_to_u32(const void* smem_ptr) {
    uint32_t addr;
    asm("{ .reg .u64 tmp; cvta.to.shared.u64 tmp, %1; cvt.u32.u64 %0, tmp; }"
        : "=r"(addr) : "l"(smem_ptr));
    return addr;
}

#define SMEM_SWIZZLE_128B(byte_offset) \
    ((byte_offset) ^ (((byte_offset) >> 3) & 0x70))

__device__ __forceinline__ void cp16(uint32_t dst, const void* src) {
    asm volatile("cp.async.cg.shared.global [%0], [%1], 16;"
                 :: "r"(dst), "l"(src) : "memory");
}
#define CP_COMMIT()  asm volatile("cp.async.commit_group;" ::: "memory")
#define CP_WAIT_1()  asm volatile("cp.async.wait_group 1;" ::: "memory")
#define CP_WAIT_0()  asm volatile("cp.async.wait_group 0;" ::: "memory")

__device__ __forceinline__ void ldsm_x4(uint32_t& r0, uint32_t& r1, uint32_t& r2,
                                        uint32_t& r3, uint32_t addr) {
    asm volatile("ldmatrix.sync.aligned.m8n8.x4.shared.b16 {%0,%1,%2,%3}, [%4];"
                 : "=r"(r0), "=r"(r1), "=r"(r2), "=r"(r3) : "r"(addr));
}
__device__ __forceinline__ void ldsm_x2(uint32_t& r0, uint32_t& r1, uint32_t addr) {
    asm volatile("ldmatrix.sync.aligned.m8n8.x2.shared.b16 {%0,%1}, [%2];"
                 : "=r"(r0), "=r"(r1) : "r"(addr));
}
__device__ __forceinline__ void mma16816(float* d, const uint32_t* a,
                                         uint32_t b0, uint32_t b1) {
    asm volatile(
        "mma.sync.aligned.m16n8k16.row.col.f32.f16.f16.f32 "
        "{%0,%1,%2,%3},{%4,%5,%6,%7},{%8,%9},{%0,%1,%2,%3};"
        : "+f"(d[0]), "+f"(d[1]), "+f"(d[2]), "+f"(d[3])
        : "r"(a[0]), "r"(a[1]), "r"(a[2]), "r"(a[3]), "r"(b0), "r"(b1));
}

// ---------------------------------------------------------------------------
// 1) router (+ perm init folded in): logits = x @ Wg^T, top-1 per token
// ---------------------------------------------------------------------------
__global__ __launch_bounds__(256) void router_kernel(const float* __restrict__ x,
                                                     const float* __restrict__ Wg) {
    // fold init: grid covers 2048*256 = 524288 >= PAD_ROWS
    int gidx = blockIdx.x * 256 + threadIdx.x;
    if (gidx < PAD_ROWS) g_perm[gidx] = -1;

    __shared__ float sWg[NEXP * DDIM];
    int tid = threadIdx.x;
    for (int i = tid; i < NEXP * DDIM; i += 256) sWg[i] = Wg[i];
    __syncthreads();

    int warp = tid >> 5, lane = tid & 31;
    int token = blockIdx.x * 8 + warp;
    if (token >= N_TOK) return;

    const float* xr = x + (size_t)token * DDIM;
    float acc[NEXP];
#pragma unroll
    for (int e = 0; e < NEXP; e++) acc[e] = 0.f;
    for (int k = lane; k < DDIM; k += 32) {
        float xv = xr[k];
#pragma unroll
        for (int e = 0; e < NEXP; e++) acc[e] += xv * sWg[e * DDIM + k];
    }
#pragma unroll
    for (int e = 0; e < NEXP; e++) {
#pragma unroll
        for (int off = 16; off > 0; off >>= 1)
            acc[e] += __shfl_xor_sync(0xFFFFFFFF, acc[e], off);
    }
    if (lane == 0) {
        int best = 0;
#pragma unroll
        for (int e = 1; e < NEXP; e++)
            if (acc[e] > acc[best]) best = e;
        g_expert[token] = (unsigned char)best;
        g_logit[token]  = acc[best];
    }
}

// ---------------------------------------------------------------------------
// 2) setup (single block, deterministic tree reduction)
// ---------------------------------------------------------------------------
__global__ __launch_bounds__(256) void setup_kernel() {
    __shared__ float sden[NEXP][256];
    __shared__ int   scnt[NEXP][256];
    int tid = threadIdx.x;

    float den[NEXP]; int cnt[NEXP];
#pragma unroll
    for (int e = 0; e < NEXP; e++) { den[e] = 0.f; cnt[e] = 0; }
    for (int t = tid; t < N_TOK; t += 256) {
        int e = g_expert[t];
        den[e] += g_logit[t];
        cnt[e]++;
    }
#pragma unroll
    for (int e = 0; e < NEXP; e++) { sden[e][tid] = den[e]; scnt[e][tid] = cnt[e]; }
    __syncthreads();
    for (int s = 128; s > 0; s >>= 1) {
        if (tid < s) {
#pragma unroll
            for (int e = 0; e < NEXP; e++) {
                sden[e][tid] += sden[e][tid + s];
                scnt[e][tid] += scnt[e][tid + s];
            }
        }
        __syncthreads();
    }
    if (tid == 0) {
        int off = 0;
        for (int e = 0; e < NEXP; e++) {
            g_denom_inv[e] = CAP / (sden[e][0] + EPSV);
            g_off[e] = off;
            g_ctr[e] = off;
            off += ((scnt[e][0] + 127) >> 7) << 7;
        }
        g_off[NEXP] = off;
    }
}

// ---------------------------------------------------------------------------
// 3) scatter
// ---------------------------------------------------------------------------
__global__ void scatter_kernel() {
    int t = blockIdx.x * blockDim.x + threadIdx.x;
    if (t >= N_TOK) return;
    int e = g_expert[t];
    int pos = atomicAdd(&g_ctr[e], 1);
    g_perm[pos] = t;
}

// ---------------------------------------------------------------------------
// 4) gather x into sorted order, convert to fp16
// ---------------------------------------------------------------------------
__global__ __launch_bounds__(128) void gather_x_kernel(const float* __restrict__ x) {
    int r = blockIdx.x;
    int t = threadIdx.x;
    int tok = g_perm[r];
    float4 v = make_float4(0.f, 0.f, 0.f, 0.f);
    if (tok >= 0) v = *(const float4*)(x + (size_t)tok * DDIM + t * 4);

    __half2 h01 = __floats2half2_rn(v.x, v.y);
    __half2 h23 = __floats2half2_rn(v.z, v.w);
    uint2 hh;
    hh.x = *(uint32_t*)&h01; hh.y = *(uint32_t*)&h23;
    *(uint2*)(g_X + (size_t)r * DDIM + t * 4) = hh;
}

// ---------------------------------------------------------------------------
// 5) fused transpose+split of BOTH weights (one launch):
//    W1 [E][D][F] -> W1T [E][F][D] fp16 hi/lo  (tiles 0..1023)
//    W2 [E][F][D] -> W2T [E][D][F] fp16 hi/lo  (tiles 1024..2047)
// ---------------------------------------------------------------------------
__global__ __launch_bounds__(256) void trans_conv_kernel(const float* __restrict__ W1,
                                                         const float* __restrict__ W2) {
    __shared__ float tile[32][33];
    int t = blockIdx.x;
    int e = blockIdx.y;

    const float* in;
    __half *hiOut, *loOut;
    int R, C, c0, r0;
    if (t < 1024) {                    // W1: R=DDIM, C=FDIM; tiles (C/32=64) x (R/32=16)
        in = W1; hiOut = g_W1Thi; loOut = g_W1Tlo;
        R = DDIM; C = FDIM;
        c0 = (t & 63) * 32;
        r0 = (t >> 6) * 32;
    } else {                           // W2: R=FDIM, C=DDIM; tiles (C/32=16) x (R/32=64)
        int u = t - 1024;
        in = W2; hiOut = g_W2Thi; loOut = g_W2Tlo;
        R = FDIM; C = DDIM;
        c0 = (u & 15) * 32;
        r0 = (u >> 4) * 32;
    }

    int tx = threadIdx.x & 31;
    int ty8 = threadIdx.x >> 5;

    const float* src = in + ((size_t)e * R + r0) * C + c0;
#pragma unroll
    for (int i = 0; i < 32; i += 8)
        tile[ty8 + i][tx] = src[(size_t)(ty8 + i) * C + tx];
    __syncthreads();

    size_t ob = ((size_t)e * C + c0) * R + r0;
#pragma unroll
    for (int i = 0; i < 32; i += 8) {
        float f = tile[tx][ty8 + i];
        __half h = __float2half_rn(f);
        __half l = __float2half_rn(f - __half2float(h));
        hiOut[ob + (size_t)(ty8 + i) * R + tx] = h;
        loOut[ob + (size_t)(ty8 + i) * R + tx] = l;
    }
}

// ---------------------------------------------------------------------------
// HMMA grouped GEMM, fp16 2-pass split precision (A single fp16, B hi/lo):
//   C[128 x 128 tile] = A[128 x KTOT] @ B^T  (B: [N][K] K-major)
// cp.async 3-stage pipeline, one sync per chunk; ldmatrix + mma.sync;
// 8 warps, warp tile 64 x 32 (2 m-warps x 4 n-warps); pass-outermost MMAs.
//   FINAL=false: A = g_X (sorted), B = W1T, epilogue relu(+b1) -> g_H fp16
//   FINAL=true : A = g_H,          B = W2T, epilogue scale*(+b2) -> scatter to out
//
// smem per stage (48KB): A 16K | Bhi 16K | Blo 16K
// dynamic layout: [0,512) token ids (FINAL) | [1024 + p*49152) stages (3)
// ---------------------------------------------------------------------------
#define STAGE_BYTES 49152
#define SMEM_GEMM_BYTES (1024 + 3 * STAGE_BYTES)   // 148480

template<int KTOT, bool FINAL>
__global__ __launch_bounds__(256, 1) void moe_gemm_kernel(
    const float* __restrict__ bias,   // [E][NTOT]
    float* __restrict__ fout)         // FINAL: [N_TOK][DDIM]
{
    constexpr int NTOT = FINAL ? DDIM : FDIM;
    extern __shared__ char smem[];
    uint32_t sbase = smem_to_u32(smem);
    int tid = threadIdx.x;
    int lane = tid & 31, wid = tid >> 5;

    int row0 = blockIdx.x * 128;
    int total = g_off[NEXP];
    if (row0 >= total) return;
    int e = 0;
    while (g_off[e + 1] <= row0) e++;
    int bn = blockIdx.y * 128;

    if (FINAL && tid < 128) ((int*)smem)[tid] = g_perm[row0 + tid];

    const __half* A   = (FINAL ? g_H : g_X) + (size_t)row0 * KTOT;
    const __half* Bhi = (FINAL ? g_W2Thi : g_W1Thi) + ((size_t)e * NTOT + bn) * KTOT;
    const __half* Blo = (FINAL ? g_W2Tlo : g_W1Tlo) + ((size_t)e * NTOT + bn) * KTOT;

    const int nC = KTOT / 64;

    // warp tile: 64 (m) x 32 (n); warps laid out 2 (m) x 4 (n)
    int wm = (wid & 1) * 64;
    int wn = (wid >> 1) * 32;

    float acc[4][4][4];
#pragma unroll
    for (int mi = 0; mi < 4; mi++)
#pragma unroll
        for (int ni = 0; ni < 4; ni++)
#pragma unroll
            for (int q = 0; q < 4; q++) acc[mi][ni][q] = 0.f;

    // --- async load of one 64-wide K chunk into stage p ---
    auto load_chunk = [&](int c, int p) {
        int kt = c * 64;
        uint32_t base = sbase + 1024 + p * STAGE_BYTES;
#pragma unroll
        for (int i = 0; i < 4; i++) {
            int u = tid + i * 256;          // 0..1023
            int r = u >> 3, s = u & 7;      // row, 16B-chunk
            uint32_t sw = SMEM_SWIZZLE_128B((uint32_t)(r * 128 + s * 16));
            size_t goff = (size_t)r * KTOT + kt + s * 8;
            cp16(base +         sw, A   + goff);
            cp16(base + 16384 + sw, Bhi + goff);
            cp16(base + 32768 + sw, Blo + goff);
        }
    };

    // --- compute one staged chunk (4 k-steps of 16) ---
    auto compute_chunk = [&](int p) {
        uint32_t aB   = sbase + 1024 + p * STAGE_BYTES;
        uint32_t bHiB = aB + 16384;
        uint32_t bLoB = aB + 32768;
#pragma unroll
        for (int ks = 0; ks < 4; ks++) {
            int k0 = ks * 16;
            uint32_t Ah[4][4];
#pragma unroll
            for (int mi = 0; mi < 4; mi++) {
                int row = wm + mi * 16 + (lane & 15);
                int colb = (k0 + (lane >> 4) * 8) * 2;
                uint32_t off = SMEM_SWIZZLE_128B((uint32_t)(row * 128 + colb));
                ldsm_x4(Ah[mi][0], Ah[mi][1], Ah[mi][2], Ah[mi][3], aB + off);
            }
            uint32_t Bh[4][2], Bl[4][2];
#pragma unroll
            for (int ni = 0; ni < 4; ni++) {
                int row = wn + ni * 8 + (lane & 7);
                int colb = (k0 + ((lane >> 3) & 1) * 8) * 2;
                uint32_t off = SMEM_SWIZZLE_128B((uint32_t)(row * 128 + colb));
                ldsm_x2(Bh[ni][0], Bh[ni][1], bHiB + off);
                ldsm_x2(Bl[ni][0], Bl[ni][1], bLoB + off);
            }
            // pass-outermost: 16 independent MMAs between same-acc touches
#pragma unroll
            for (int mi = 0; mi < 4; mi++)
#pragma unroll
                for (int ni = 0; ni < 4; ni++)
                    mma16816(acc[mi][ni], Ah[mi], Bh[ni][0], Bh[ni][1]);  // A*Bhi
#pragma unroll
            for (int mi = 0; mi < 4; mi++)
#pragma unroll
                for (int ni = 0; ni < 4; ni++)
                    mma16816(acc[mi][ni], Ah[mi], Bl[ni][0], Bl[ni][1]);  // A*Blo
        }
    };

    // --- 3-stage pipeline, one __syncthreads per chunk ---
    load_chunk(0, 0);
    CP_COMMIT();
    if (nC > 1) { load_chunk(1, 1); CP_COMMIT(); }
    for (int c = 0; c < nC; c++) {
        if (c + 1 < nC) CP_WAIT_1(); else CP_WAIT_0();
        __syncthreads();
        if (c + 2 < nC) { load_chunk(c + 2, (c + 2) % 3); CP_COMMIT(); }
        compute_chunk(c % 3);
    }

    // --- epilogue ---
    int gq = lane >> 2;          // 0..7  (row group)
    int t4 = lane & 3;           // 0..3  (column pair)
    float dinv = FINAL ? g_denom_inv[e] : 0.f;
    const int* sTok = (const int*)smem;

#pragma unroll
    for (int mi = 0; mi < 4; mi++) {
        int rA = wm + mi * 16 + gq;       // local row for d0,d1
        int rB = rA + 8;                  // local row for d2,d3
        int tok0 = 0, tok1 = 0;
        float sc0 = 0.f, sc1 = 0.f;
        if (FINAL) {
            tok0 = sTok[rA]; tok1 = sTok[rB];
            if (tok0 >= 0) sc0 = g_logit[tok0] * dinv;
            if (tok1 >= 0) sc1 = g_logit[tok1] * dinv;
        }
#pragma unroll
        for (int ni = 0; ni < 4; ni++) {
            int gcol = bn + wn + ni * 8 + t4 * 2;
            float2 bv = __ldg((const float2*)(bias + (size_t)e * NTOT + gcol));
            float* d = acc[mi][ni];
            if (FINAL) {
                if (tok0 >= 0) {
                    float2 v = make_float2(sc0 * (d[0] + bv.x), sc0 * (d[1] + bv.y));
                    *(float2*)(fout + (size_t)tok0 * DDIM + gcol) = v;
                }
                if (tok1 >= 0) {
                    float2 v = make_float2(sc1 * (d[2] + bv.x), sc1 * (d[3] + bv.y));
                    *(float2*)(fout + (size_t)tok1 * DDIM + gcol) = v;
                }
            } else {
                float f0 = d[0] + bv.x; f0 = f0 > 0.f ? f0 : 0.f;
                float f1 = d[1] + bv.y; f1 = f1 > 0.f ? f1 : 0.f;
                float f2 = d[2] + bv.x; f2 = f2 > 0.f ? f2 : 0.f;
                float f3 = d[3] + bv.y; f3 = f3 > 0.f ? f3 : 0.f;

                __half2 h01 = __floats2half2_rn(f0, f1);
                __half2 h23 = __floats2half2_rn(f2, f3);
                *(uint32_t*)(g_H + (size_t)(row0 + rA) * FDIM + gcol) = *(uint32_t*)&h01;
                *(uint32_t*)(g_H + (size_t)(row0 + rB) * FDIM + gcol) = *(uint32_t*)&h23;
            }
        }
    }
}

// ---------------------------------------------------------------------------
extern "C" void kernel_launch(void* const* d_in, const int* in_sizes, int n_in,
                              void* d_out, int out_size) {
    const float* x  = (const float*)d_in[0];   // [N, D]
    const float* Wg = (const float*)d_in[1];   // [E, D]
    const float* W1 = (const float*)d_in[2];   // [E, D, F]
    const float* b1 = (const float*)d_in[3];   // [E, F]
    const float* W2 = (const float*)d_in[4];   // [E, F, D]
    const float* b2 = (const float*)d_in[5];   // [E, D]
    float* out = (float*)d_out;                // [N, D]

    cudaFuncSetAttribute(moe_gemm_kernel<DDIM, false>,
                         cudaFuncAttributeMaxDynamicSharedMemorySize, SMEM_GEMM_BYTES);
    cudaFuncSetAttribute(moe_gemm_kernel<FDIM, true>,
                         cudaFuncAttributeMaxDynamicSharedMemorySize, SMEM_GEMM_BYTES);

    // launch order arranged so gemm1 is the 6th launch (ncu -s 5 -c 1 captures it)
    router_kernel<<<N_TOK / 8, 256>>>(x, Wg);                       // 1 (also inits perm)
    setup_kernel<<<1, 256>>>();                                     // 2
    scatter_kernel<<<N_TOK / 256, 256>>>();                         // 3
    gather_x_kernel<<<PAD_ROWS, 128>>>(x);                          // 4
    trans_conv_kernel<<<dim3(2048, NEXP), 256>>>(W1, W2);           // 5

    moe_gemm_kernel<DDIM, false><<<dim3(MAX_TILES, FDIM / 128), 256, SMEM_GEMM_BYTES>>>(b1, nullptr);   // 6
    moe_gemm_kernel<FDIM, true><<<dim3(MAX_TILES, DDIM / 128), 256, SMEM_GEMM_BYTES>>>(b2, out);        // 7
}

// round 12
// speedup vs baseline: 2.0569x; 1.3608x over previous
#include <cuda_runtime.h>
#include <cuda_fp16.h>
#include <cstdint>

// ---------------- problem constants ----------------
#define N_TOK  16384
#define DDIM   512
#define FDIM   2048
#define NEXP   8
#define CAP    16384.0f
#define EPSV   1e-6f

#define PAD_ROWS (N_TOK + NEXP * 128)   // 17408
#define MAX_TILES (PAD_ROWS / 128)      // 136

// ---------------- scratch (device globals; 16B-access aligned) ----------------
__device__ unsigned char g_expert[N_TOK];
__device__ float g_logit[N_TOK];
__device__ float g_denom_inv[NEXP];
__device__ int   g_off[NEXP + 1];
__device__ int   g_ctr[NEXP];
__device__ int   g_perm[PAD_ROWS];

__device__ __align__(256) __half g_X[(size_t)PAD_ROWS * DDIM];        // gathered x, fp16
__device__ __align__(256) __half g_H[(size_t)PAD_ROWS * FDIM];        // hidden, fp16
__device__ __align__(256) __half g_W1T[(size_t)NEXP * FDIM * DDIM];   // [E][F][D]
__device__ __align__(256) __half g_W2T[(size_t)NEXP * DDIM * FDIM];   // [E][D][F]

// ---------------- helpers ----------------
__device__ __forceinline__ uint32_t smem_to_u32(const void* smem_ptr) {
    uint32_t addr;
    asm("{ .reg .u64 tmp; cvta.to.shared.u64 tmp, %1; cvt.u32.u64 %0, tmp; }"
        : "=r"(addr) : "l"(smem_ptr));
    return addr;
}

#define SMEM_SWIZZLE_128B(byte_offset) \
    ((byte_offset) ^ (((byte_offset) >> 3) & 0x70))

__device__ __forceinline__ void cp16(uint32_t dst, const void* src) {
    asm volatile("cp.async.cg.shared.global [%0], [%1], 16;"
                 :: "r"(dst), "l"(src) : "memory");
}
#define CP_COMMIT()  asm volatile("cp.async.commit_group;" ::: "memory")
#define CP_WAIT_1()  asm volatile("cp.async.wait_group 1;" ::: "memory")
#define CP_WAIT_0()  asm volatile("cp.async.wait_group 0;" ::: "memory")

__device__ __forceinline__ void ldsm_x4(uint32_t& r0, uint32_t& r1, uint32_t& r2,
                                        uint32_t& r3, uint32_t addr) {
    asm volatile("ldmatrix.sync.aligned.m8n8.x4.shared.b16 {%0,%1,%2,%3}, [%4];"
                 : "=r"(r0), "=r"(r1), "=r"(r2), "=r"(r3) : "r"(addr));
}
__device__ __forceinline__ void ldsm_x2(uint32_t& r0, uint32_t& r1, uint32_t addr) {
    asm volatile("ldmatrix.sync.aligned.m8n8.x2.shared.b16 {%0,%1}, [%2];"
                 : "=r"(r0), "=r"(r1) : "r"(addr));
}
__device__ __forceinline__ void mma16816(float* d, const uint32_t* a,
                                         uint32_t b0, uint32_t b1) {
    asm volatile(
        "mma.sync.aligned.m16n8k16.row.col.f32.f16.f16.f32 "
        "{%0,%1,%2,%3},{%4,%5,%6,%7},{%8,%9},{%0,%1,%2,%3};"
        : "+f"(d[0]), "+f"(d[1]), "+f"(d[2]), "+f"(d[3])
        : "r"(a[0]), "r"(a[1]), "r"(a[2]), "r"(a[3]), "r"(b0), "r"(b1));
}

// ---------------------------------------------------------------------------
// 1) router (+ perm init folded in): logits = x @ Wg^T, top-1 per token
// ---------------------------------------------------------------------------
__global__ __launch_bounds__(256) void router_kernel(const float* __restrict__ x,
                                                     const float* __restrict__ Wg) {
    int gidx = blockIdx.x * 256 + threadIdx.x;
    if (gidx < PAD_ROWS) g_perm[gidx] = -1;

    __shared__ float sWg[NEXP * DDIM];
    int tid = threadIdx.x;
    for (int i = tid; i < NEXP * DDIM; i += 256) sWg[i] = Wg[i];
    __syncthreads();

    int warp = tid >> 5, lane = tid & 31;
    int token = blockIdx.x * 8 + warp;
    if (token >= N_TOK) return;

    const float* xr = x + (size_t)token * DDIM;
    float acc[NEXP];
#pragma unroll
    for (int e = 0; e < NEXP; e++) acc[e] = 0.f;
    for (int k = lane; k < DDIM; k += 32) {
        float xv = xr[k];
#pragma unroll
        for (int e = 0; e < NEXP; e++) acc[e] += xv * sWg[e * DDIM + k];
    }
#pragma unroll
    for (int e = 0; e < NEXP; e++) {
#pragma unroll
        for (int off = 16; off > 0; off >>= 1)
            acc[e] += __shfl_xor_sync(0xFFFFFFFF, acc[e], off);
    }
    if (lane == 0) {
        int best = 0;
#pragma unroll
        for (int e = 1; e < NEXP; e++)
            if (acc[e] > acc[best]) best = e;
        g_expert[token] = (unsigned char)best;
        g_logit[token]  = acc[best];
    }
}

// ---------------------------------------------------------------------------
// 2) setup (single block, deterministic tree reduction)
// ---------------------------------------------------------------------------
__global__ __launch_bounds__(256) void setup_kernel() {
    __shared__ float sden[NEXP][256];
    __shared__ int   scnt[NEXP][256];
    int tid = threadIdx.x;

    float den[NEXP]; int cnt[NEXP];
#pragma unroll
    for (int e = 0; e < NEXP; e++) { den[e] = 0.f; cnt[e] = 0; }
    for (int t = tid; t < N_TOK; t += 256) {
        int e = g_expert[t];
        den[e] += g_logit[t];
        cnt[e]++;
    }
#pragma unroll
    for (int e = 0; e < NEXP; e++) { sden[e][tid] = den[e]; scnt[e][tid] = cnt[e]; }
    __syncthreads();
    for (int s = 128; s > 0; s >>= 1) {
        if (tid < s) {
#pragma unroll
            for (int e = 0; e < NEXP; e++) {
                sden[e][tid] += sden[e][tid + s];
                scnt[e][tid] += scnt[e][tid + s];
            }
        }
        __syncthreads();
    }
    if (tid == 0) {
        int off = 0;
        for (int e = 0; e < NEXP; e++) {
            g_denom_inv[e] = CAP / (sden[e][0] + EPSV);
            g_off[e] = off;
            g_ctr[e] = off;
            off += ((scnt[e][0] + 127) >> 7) << 7;
        }
        g_off[NEXP] = off;
    }
}

// ---------------------------------------------------------------------------
// 3) scatter
// ---------------------------------------------------------------------------
__global__ void scatter_kernel() {
    int t = blockIdx.x * blockDim.x + threadIdx.x;
    if (t >= N_TOK) return;
    int e = g_expert[t];
    int pos = atomicAdd(&g_ctr[e], 1);
    g_perm[pos] = t;
}

// ---------------------------------------------------------------------------
// 4) gather x into sorted order, convert to fp16
// ---------------------------------------------------------------------------
__global__ __launch_bounds__(128) void gather_x_kernel(const float* __restrict__ x) {
    int r = blockIdx.x;
    int t = threadIdx.x;
    int tok = g_perm[r];
    float4 v = make_float4(0.f, 0.f, 0.f, 0.f);
    if (tok >= 0) v = *(const float4*)(x + (size_t)tok * DDIM + t * 4);

    __half2 h01 = __floats2half2_rn(v.x, v.y);
    __half2 h23 = __floats2half2_rn(v.z, v.w);
    uint2 hh;
    hh.x = *(uint32_t*)&h01; hh.y = *(uint32_t*)&h23;
    *(uint2*)(g_X + (size_t)r * DDIM + t * 4) = hh;
}

// ---------------------------------------------------------------------------
// 5) fused transpose+convert of BOTH weights (one launch, fp16 single):
//    W1 [E][D][F] -> W1T [E][F][D]   (tiles 0..1023)
//    W2 [E][F][D] -> W2T [E][D][F]   (tiles 1024..2047)
// ---------------------------------------------------------------------------
__global__ __launch_bounds__(256) void trans_conv_kernel(const float* __restrict__ W1,
                                                         const float* __restrict__ W2) {
    __shared__ float tile[32][33];
    int t = blockIdx.x;
    int e = blockIdx.y;

    const float* in;
    __half* out;
    int R, C, c0, r0;
    if (t < 1024) {                    // W1: R=DDIM, C=FDIM; tiles (C/32=64) x (R/32=16)
        in = W1; out = g_W1T;
        R = DDIM; C = FDIM;
        c0 = (t & 63) * 32;
        r0 = (t >> 6) * 32;
    } else {                           // W2: R=FDIM, C=DDIM; tiles (C/32=16) x (R/32=64)
        int u = t - 1024;
        in = W2; out = g_W2T;
        R = FDIM; C = DDIM;
        c0 = (u & 15) * 32;
        r0 = (u >> 4) * 32;
    }

    int tx = threadIdx.x & 31;
    int ty8 = threadIdx.x >> 5;

    const float* src = in + ((size_t)e * R + r0) * C + c0;
#pragma unroll
    for (int i = 0; i < 32; i += 8)
        tile[ty8 + i][tx] = src[(size_t)(ty8 + i) * C + tx];
    __syncthreads();

    size_t ob = ((size_t)e * C + c0) * R + r0;
#pragma unroll
    for (int i = 0; i < 32; i += 8)
        out[ob + (size_t)(ty8 + i) * R + tx] = __float2half_rn(tile[tx][ty8 + i]);
}

// ---------------------------------------------------------------------------
// HMMA grouped GEMM, pure fp16 single pass:
//   C[128 x 128 tile] = A[128 x KTOT] @ B^T  (B: [N][K] K-major)
// cp.async 3-stage pipeline, one sync per chunk; ldmatrix + mma.sync;
// 8 warps, warp tile 64 x 32 (2 m-warps x 4 n-warps).
//   FINAL=false: A = g_X (sorted), B = W1T, epilogue relu(+b1) -> g_H fp16
//   FINAL=true : A = g_H,          B = W2T, epilogue scale*(+b2) -> scatter to out
//
// smem per stage (32KB): A 16K | B 16K
// dynamic layout: [0,512) token ids (FINAL) | [1024 + p*32768) stages (3)
// ---------------------------------------------------------------------------
#define STAGE_BYTES 32768
#define SMEM_GEMM_BYTES (1024 + 3 * STAGE_BYTES)   // 99328

template<int KTOT, bool FINAL>
__global__ __launch_bounds__(256, 1) void moe_gemm_kernel(
    const float* __restrict__ bias,   // [E][NTOT]
    float* __restrict__ fout)         // FINAL: [N_TOK][DDIM]
{
    constexpr int NTOT = FINAL ? DDIM : FDIM;
    extern __shared__ char smem[];
    uint32_t sbase = smem_to_u32(smem);
    int tid = threadIdx.x;
    int lane = tid & 31, wid = tid >> 5;

    int row0 = blockIdx.x * 128;
    int total = g_off[NEXP];
    if (row0 >= total) return;
    int e = 0;
    while (g_off[e + 1] <= row0) e++;
    int bn = blockIdx.y * 128;

    if (FINAL && tid < 128) ((int*)smem)[tid] = g_perm[row0 + tid];

    const __half* A = (FINAL ? g_H : g_X) + (size_t)row0 * KTOT;
    const __half* B = (FINAL ? g_W2T : g_W1T) + ((size_t)e * NTOT + bn) * KTOT;

    const int nC = KTOT / 64;

    // warp tile: 64 (m) x 32 (n); warps laid out 2 (m) x 4 (n)
    int wm = (wid & 1) * 64;
    int wn = (wid >> 1) * 32;

    float acc[4][4][4];
#pragma unroll
    for (int mi = 0; mi < 4; mi++)
#pragma unroll
        for (int ni = 0; ni < 4; ni++)
#pragma unroll
            for (int q = 0; q < 4; q++) acc[mi][ni][q] = 0.f;

    // --- async load of one 64-wide K chunk into stage p ---
    auto load_chunk = [&](int c, int p) {
        int kt = c * 64;
        uint32_t base = sbase + 1024 + p * STAGE_BYTES;
#pragma unroll
        for (int i = 0; i < 4; i++) {
            int u = tid + i * 256;          // 0..1023
            int r = u >> 3, s = u & 7;      // row, 16B-chunk
            uint32_t sw = SMEM_SWIZZLE_128B((uint32_t)(r * 128 + s * 16));
            size_t goff = (size_t)r * KTOT + kt + s * 8;
            cp16(base +         sw, A + goff);
            cp16(base + 16384 + sw, B + goff);
        }
    };

    // --- compute one staged chunk (4 k-steps of 16) ---
    auto compute_chunk = [&](int p) {
        uint32_t aB = sbase + 1024 + p * STAGE_BYTES;
        uint32_t bB = aB + 16384;
#pragma unroll
        for (int ks = 0; ks < 4; ks++) {
            int k0 = ks * 16;
            uint32_t Ah[4][4];
#pragma unroll
            for (int mi = 0; mi < 4; mi++) {
                int row = wm + mi * 16 + (lane & 15);
                int colb = (k0 + (lane >> 4) * 8) * 2;
                uint32_t off = SMEM_SWIZZLE_128B((uint32_t)(row * 128 + colb));
                ldsm_x4(Ah[mi][0], Ah[mi][1], Ah[mi][2], Ah[mi][3], aB + off);
            }
            uint32_t Bh[4][2];
#pragma unroll
            for (int ni = 0; ni < 4; ni++) {
                int row = wn + ni * 8 + (lane & 7);
                int colb = (k0 + ((lane >> 3) & 1) * 8) * 2;
                uint32_t off = SMEM_SWIZZLE_128B((uint32_t)(row * 128 + colb));
                ldsm_x2(Bh[ni][0], Bh[ni][1], bB + off);
            }
#pragma unroll
            for (int mi = 0; mi < 4; mi++)
#pragma unroll
                for (int ni = 0; ni < 4; ni++)
                    mma16816(acc[mi][ni], Ah[mi], Bh[ni][0], Bh[ni][1]);
        }
    };

    // --- 3-stage pipeline, one __syncthreads per chunk ---
    load_chunk(0, 0);
    CP_COMMIT();
    if (nC > 1) { load_chunk(1, 1); CP_COMMIT(); }
    for (int c = 0; c < nC; c++) {
        if (c + 1 < nC) CP_WAIT_1(); else CP_WAIT_0();
        __syncthreads();
        if (c + 2 < nC) { load_chunk(c + 2, (c + 2) % 3); CP_COMMIT(); }
        compute_chunk(c % 3);
    }

    // --- epilogue ---
    int gq = lane >> 2;          // 0..7  (row group)
    int t4 = lane & 3;           // 0..3  (column pair)
    float dinv = FINAL ? g_denom_inv[e] : 0.f;
    const int* sTok = (const int*)smem;

#pragma unroll
    for (int mi = 0; mi < 4; mi++) {
        int rA = wm + mi * 16 + gq;       // local row for d0,d1
        int rB = rA + 8;                  // local row for d2,d3
        int tok0 = 0, tok1 = 0;
        float sc0 = 0.f, sc1 = 0.f;
        if (FINAL) {
            tok0 = sTok[rA]; tok1 = sTok[rB];
            if (tok0 >= 0) sc0 = g_logit[tok0] * dinv;
            if (tok1 >= 0) sc1 = g_logit[tok1] * dinv;
        }
#pragma unroll
        for (int ni = 0; ni < 4; ni++) {
            int gcol = bn + wn + ni * 8 + t4 * 2;
            float2 bv = __ldg((const float2*)(bias + (size_t)e * NTOT + gcol));
            float* d = acc[mi][ni];
            if (FINAL) {
                if (tok0 >= 0) {
                    float2 v = make_float2(sc0 * (d[0] + bv.x), sc0 * (d[1] + bv.y));
                    *(float2*)(fout + (size_t)tok0 * DDIM + gcol) = v;
                }
                if (tok1 >= 0) {
                    float2 v = make_float2(sc1 * (d[2] + bv.x), sc1 * (d[3] + bv.y));
                    *(float2*)(fout + (size_t)tok1 * DDIM + gcol) = v;
                }
            } else {
                float f0 = d[0] + bv.x; f0 = f0 > 0.f ? f0 : 0.f;
                float f1 = d[1] + bv.y; f1 = f1 > 0.f ? f1 : 0.f;
                float f2 = d[2] + bv.x; f2 = f2 > 0.f ? f2 : 0.f;
                float f3 = d[3] + bv.y; f3 = f3 > 0.f ? f3 : 0.f;

                __half2 h01 = __floats2half2_rn(f0, f1);
                __half2 h23 = __floats2half2_rn(f2, f3);
                *(uint32_t*)(g_H + (size_t)(row0 + rA) * FDIM + gcol) = *(uint32_t*)&h01;
                *(uint32_t*)(g_H + (size_t)(row0 + rB) * FDIM + gcol) = *(uint32_t*)&h23;
            }
        }
    }
}

// ---------------------------------------------------------------------------
extern "C" void kernel_launch(void* const* d_in, const int* in_sizes, int n_in,
                              void* d_out, int out_size) {
    const float* x  = (const float*)d_in[0];   // [N, D]
    const float* Wg = (const float*)d_in[1];   // [E, D]
    const float* W1 = (const float*)d_in[2];   // [E, D, F]
    const float* b1 = (const float*)d_in[3];   // [E, F]
    const float* W2 = (const float*)d_in[4];   // [E, F, D]
    const float* b2 = (const float*)d_in[5];   // [E, D]
    float* out = (float*)d_out;                // [N, D]

    cudaFuncSetAttribute(moe_gemm_kernel<DDIM, false>,
                         cudaFuncAttributeMaxDynamicSharedMemorySize, SMEM_GEMM_BYTES);
    cudaFuncSetAttribute(moe_gemm_kernel<FDIM, true>,
                         cudaFuncAttributeMaxDynamicSharedMemorySize, SMEM_GEMM_BYTES);

    // launch order keeps gemm1 as the 6th launch (ncu -s 5 -c 1 captures it)
    router_kernel<<<N_TOK / 8, 256>>>(x, Wg);                       // 1 (also inits perm)
    setup_kernel<<<1, 256>>>();                                     // 2
    scatter_kernel<<<N_TOK / 256, 256>>>();                         // 3
    gather_x_kernel<<<PAD_ROWS, 128>>>(x);                          // 4
    trans_conv_kernel<<<dim3(2048, NEXP), 256>>>(W1, W2);           // 5

    moe_gemm_kernel<DDIM, false><<<dim3(MAX_TILES, FDIM / 128), 256, SMEM_GEMM_BYTES>>>(b1, nullptr);   // 6
    moe_gemm_kernel<FDIM, true><<<dim3(MAX_TILES, DDIM / 128), 256, SMEM_GEMM_BYTES>>>(b2, out);        // 7
}

// round 13
// speedup vs baseline: 2.2212x; 1.0799x over previous
#include <cuda_runtime.h>
#include <cuda_fp16.h>
#include <cstdint>

// ---------------- problem constants ----------------
#define N_TOK  16384
#define DDIM   512
#define FDIM   2048
#define NEXP   8
#define CAP    16384.0f
#define EPSV   1e-6f

#define PAD_ROWS (N_TOK + NEXP * 256)   // 18432
#define MAX_TILES (PAD_ROWS / 256)      // 72

// ---------------- scratch (device globals; 16B-access aligned) ----------------
__device__ unsigned char g_expert[N_TOK];
__device__ float g_logit[N_TOK];
__device__ float g_denom_inv[NEXP];
__device__ int   g_off[NEXP + 1];
__device__ int   g_ctr[NEXP];
__device__ int   g_perm[PAD_ROWS];

__device__ __align__(256) __half g_X[(size_t)PAD_ROWS * DDIM];        // gathered x, fp16
__device__ __align__(256) __half g_H[(size_t)PAD_ROWS * FDIM];        // hidden, fp16
__device__ __align__(256) __half g_W1T[(size_t)NEXP * FDIM * DDIM];   // [E][F][D]
__device__ __align__(256) __half g_W2T[(size_t)NEXP * DDIM * FDIM];   // [E][D][F]

// ---------------- helpers ----------------
__device__ __forceinline__ uint32_t smem_to_u32(const void* smem_ptr) {
    uint32_t addr;
    asm("{ .reg .u64 tmp; cvta.to.shared.u64 tmp, %1; cvt.u32.u64 %0, tmp; }"
        : "=r"(addr) : "l"(smem_ptr));
    return addr;
}

#define SMEM_SWIZZLE_128B(byte_offset) \
    ((byte_offset) ^ (((byte_offset) >> 3) & 0x70))

__device__ __forceinline__ void cp16(uint32_t dst, const void* src) {
    asm volatile("cp.async.cg.shared.global [%0], [%1], 16;"
                 :: "r"(dst), "l"(src) : "memory");
}
#define CP_COMMIT()  asm volatile("cp.async.commit_group;" ::: "memory")
#define CP_WAIT_1()  asm volatile("cp.async.wait_group 1;" ::: "memory")
#define CP_WAIT_0()  asm volatile("cp.async.wait_group 0;" ::: "memory")

__device__ __forceinline__ void ldsm_x4(uint32_t& r0, uint32_t& r1, uint32_t& r2,
                                        uint32_t& r3, uint32_t addr) {
    asm volatile("ldmatrix.sync.aligned.m8n8.x4.shared.b16 {%0,%1,%2,%3}, [%4];"
                 : "=r"(r0), "=r"(r1), "=r"(r2), "=r"(r3) : "r"(addr));
}
__device__ __forceinline__ void ldsm_x2(uint32_t& r0, uint32_t& r1, uint32_t addr) {
    asm volatile("ldmatrix.sync.aligned.m8n8.x2.shared.b16 {%0,%1}, [%2];"
                 : "=r"(r0), "=r"(r1) : "r"(addr));
}
__device__ __forceinline__ void mma16816(float* d, const uint32_t* a,
                                         uint32_t b0, uint32_t b1) {
    asm volatile(
        "mma.sync.aligned.m16n8k16.row.col.f32.f16.f16.f32 "
        "{%0,%1,%2,%3},{%4,%5,%6,%7},{%8,%9},{%0,%1,%2,%3};"
        : "+f"(d[0]), "+f"(d[1]), "+f"(d[2]), "+f"(d[3])
        : "r"(a[0]), "r"(a[1]), "r"(a[2]), "r"(a[3]), "r"(b0), "r"(b1));
}

// ---------------------------------------------------------------------------
// 1) router (+ perm init folded in): logits = x @ Wg^T, top-1 per token
// ---------------------------------------------------------------------------
__global__ __launch_bounds__(256) void router_kernel(const float* __restrict__ x,
                                                     const float* __restrict__ Wg) {
    int gidx = blockIdx.x * 256 + threadIdx.x;
    if (gidx < PAD_ROWS) g_perm[gidx] = -1;

    __shared__ float sWg[NEXP * DDIM];
    int tid = threadIdx.x;
    for (int i = tid; i < NEXP * DDIM; i += 256) sWg[i] = Wg[i];
    __syncthreads();

    int warp = tid >> 5, lane = tid & 31;
    int token = blockIdx.x * 8 + warp;
    if (token >= N_TOK) return;

    const float* xr = x + (size_t)token * DDIM;
    float acc[NEXP];
#pragma unroll
    for (int e = 0; e < NEXP; e++) acc[e] = 0.f;
    for (int k = lane; k < DDIM; k += 32) {
        float xv = xr[k];
#pragma unroll
        for (int e = 0; e < NEXP; e++) acc[e] += xv * sWg[e * DDIM + k];
    }
#pragma unroll
    for (int e = 0; e < NEXP; e++) {
#pragma unroll
        for (int off = 16; off > 0; off >>= 1)
            acc[e] += __shfl_xor_sync(0xFFFFFFFF, acc[e], off);
    }
    if (lane == 0) {
        int best = 0;
#pragma unroll
        for (int e = 1; e < NEXP; e++)
            if (acc[e] > acc[best]) best = e;
        g_expert[token] = (unsigned char)best;
        g_logit[token]  = acc[best];
    }
}

// ---------------------------------------------------------------------------
// 2) setup (single block, deterministic tree reduction); segments pad to 256
// ---------------------------------------------------------------------------
__global__ __launch_bounds__(256) void setup_kernel() {
    __shared__ float sden[NEXP][256];
    __shared__ int   scnt[NEXP][256];
    int tid = threadIdx.x;

    float den[NEXP]; int cnt[NEXP];
#pragma unroll
    for (int e = 0; e < NEXP; e++) { den[e] = 0.f; cnt[e] = 0; }
    for (int t = tid; t < N_TOK; t += 256) {
        int e = g_expert[t];
        den[e] += g_logit[t];
        cnt[e]++;
    }
#pragma unroll
    for (int e = 0; e < NEXP; e++) { sden[e][tid] = den[e]; scnt[e][tid] = cnt[e]; }
    __syncthreads();
    for (int s = 128; s > 0; s >>= 1) {
        if (tid < s) {
#pragma unroll
            for (int e = 0; e < NEXP; e++) {
                sden[e][tid] += sden[e][tid + s];
                scnt[e][tid] += scnt[e][tid + s];
            }
        }
        __syncthreads();
    }
    if (tid == 0) {
        int off = 0;
        for (int e = 0; e < NEXP; e++) {
            g_denom_inv[e] = CAP / (sden[e][0] + EPSV);
            g_off[e] = off;
            g_ctr[e] = off;
            off += ((scnt[e][0] + 255) >> 8) << 8;   // pad segments to 256
        }
        g_off[NEXP] = off;
    }
}

// ---------------------------------------------------------------------------
// 3) scatter
// ---------------------------------------------------------------------------
__global__ void scatter_kernel() {
    int t = blockIdx.x * blockDim.x + threadIdx.x;
    if (t >= N_TOK) return;
    int e = g_expert[t];
    int pos = atomicAdd(&g_ctr[e], 1);
    g_perm[pos] = t;
}

// ---------------------------------------------------------------------------
// 4) gather x into sorted order, convert to fp16
// ---------------------------------------------------------------------------
__global__ __launch_bounds__(128) void gather_x_kernel(const float* __restrict__ x) {
    int r = blockIdx.x;
    int t = threadIdx.x;
    int tok = g_perm[r];
    float4 v = make_float4(0.f, 0.f, 0.f, 0.f);
    if (tok >= 0) v = *(const float4*)(x + (size_t)tok * DDIM + t * 4);

    __half2 h01 = __floats2half2_rn(v.x, v.y);
    __half2 h23 = __floats2half2_rn(v.z, v.w);
    uint2 hh;
    hh.x = *(uint32_t*)&h01; hh.y = *(uint32_t*)&h23;
    *(uint2*)(g_X + (size_t)r * DDIM + t * 4) = hh;
}

// ---------------------------------------------------------------------------
// 5) fused transpose+convert of BOTH weights (one launch, fp16 single):
//    W1 [E][D][F] -> W1T [E][F][D]   (tiles 0..1023)
//    W2 [E][F][D] -> W2T [E][D][F]   (tiles 1024..2047)
// ---------------------------------------------------------------------------
__global__ __launch_bounds__(256) void trans_conv_kernel(const float* __restrict__ W1,
                                                         const float* __restrict__ W2) {
    __shared__ float tile[32][33];
    int t = blockIdx.x;
    int e = blockIdx.y;

    const float* in;
    __half* out;
    int R, C, c0, r0;
    if (t < 1024) {                    // W1: R=DDIM, C=FDIM
        in = W1; out = g_W1T;
        R = DDIM; C = FDIM;
        c0 = (t & 63) * 32;
        r0 = (t >> 6) * 32;
    } else {                           // W2: R=FDIM, C=DDIM
        int u = t - 1024;
        in = W2; out = g_W2T;
        R = FDIM; C = DDIM;
        c0 = (u & 15) * 32;
        r0 = (u >> 4) * 32;
    }

    int tx = threadIdx.x & 31;
    int ty8 = threadIdx.x >> 5;

    const float* src = in + ((size_t)e * R + r0) * C + c0;
#pragma unroll
    for (int i = 0; i < 32; i += 8)
        tile[ty8 + i][tx] = src[(size_t)(ty8 + i) * C + tx];
    __syncthreads();

    size_t ob = ((size_t)e * C + c0) * R + r0;
#pragma unroll
    for (int i = 0; i < 32; i += 8)
        out[ob + (size_t)(ty8 + i) * R + tx] = __float2half_rn(tile[tx][ty8 + i]);
}

// ---------------------------------------------------------------------------
// HMMA grouped GEMM, pure fp16 single pass, BM=256 x BN=128:
//   C[256 x 128 tile] = A[256 x KTOT] @ B^T  (B: [N][K] K-major)
// cp.async 3-stage pipeline, one sync per chunk; ldmatrix + mma.sync;
// 8 warps, warp tile 128 x 32 (2 m-warps x 4 n-warps);
// A fragments staged in two 64-row halves per k-step (caps regs ~185).
//   FINAL=false: A = g_X (sorted), B = W1T, epilogue relu(+b1) -> g_H fp16
//   FINAL=true : A = g_H,          B = W2T, epilogue scale*(+b2) -> scatter to out
//
// smem per stage (48KB): A 32K | B 16K
// dynamic layout: [0,1024) token ids (FINAL, 256 ints) | [1024 + p*49152) stages (3)
// ---------------------------------------------------------------------------
#define STAGE_BYTES 49152
#define SMEM_GEMM_BYTES (1024 + 3 * STAGE_BYTES)   // 148480

template<int KTOT, bool FINAL>
__global__ __launch_bounds__(256, 1) void moe_gemm_kernel(
    const float* __restrict__ bias,   // [E][NTOT]
    float* __restrict__ fout)         // FINAL: [N_TOK][DDIM]
{
    constexpr int NTOT = FINAL ? DDIM : FDIM;
    extern __shared__ char smem[];
    uint32_t sbase = smem_to_u32(smem);
    int tid = threadIdx.x;
    int lane = tid & 31, wid = tid >> 5;

    int row0 = blockIdx.x * 256;
    int total = g_off[NEXP];
    if (row0 >= total) return;
    int e = 0;
    while (g_off[e + 1] <= row0) e++;
    int bn = blockIdx.y * 128;

    if (FINAL) ((int*)smem)[tid] = g_perm[row0 + tid];

    const __half* A = (FINAL ? g_H : g_X) + (size_t)row0 * KTOT;
    const __half* B = (FINAL ? g_W2T : g_W1T) + ((size_t)e * NTOT + bn) * KTOT;

    const int nC = KTOT / 64;

    // warp tile: 128 (m) x 32 (n); warps laid out 2 (m) x 4 (n)
    int wm = (wid & 1) * 128;
    int wn = (wid >> 1) * 32;

    float acc[8][4][4];
#pragma unroll
    for (int mi = 0; mi < 8; mi++)
#pragma unroll
        for (int ni = 0; ni < 4; ni++)
#pragma unroll
            for (int q = 0; q < 4; q++) acc[mi][ni][q] = 0.f;

    // --- async load of one 64-wide K chunk into stage p ---
    auto load_chunk = [&](int c, int p) {
        int kt = c * 64;
        uint32_t base = sbase + 1024 + p * STAGE_BYTES;
        // A: 256 rows -> 2048 16B units
#pragma unroll
        for (int i = 0; i < 8; i++) {
            int u = tid + i * 256;
            int r = u >> 3, s = u & 7;
            uint32_t sw = SMEM_SWIZZLE_128B((uint32_t)(r * 128 + s * 16));
            cp16(base + sw, A + (size_t)r * KTOT + kt + s * 8);
        }
        // B: 128 rows -> 1024 16B units
#pragma unroll
        for (int i = 0; i < 4; i++) {
            int u = tid + i * 256;
            int r = u >> 3, s = u & 7;
            uint32_t sw = SMEM_SWIZZLE_128B((uint32_t)(r * 128 + s * 16));
            cp16(base + 32768 + sw, B + (size_t)r * KTOT + kt + s * 8);
        }
    };

    // --- compute one staged chunk (4 k-steps of 16) ---
    auto compute_chunk = [&](int p) {
        uint32_t aB = sbase + 1024 + p * STAGE_BYTES;
        uint32_t bB = aB + 32768;
#pragma unroll
        for (int ks = 0; ks < 4; ks++) {
            int k0 = ks * 16;
            uint32_t Bh[4][2];
#pragma unroll
            for (int ni = 0; ni < 4; ni++) {
                int row = wn + ni * 8 + (lane & 7);
                int colb = (k0 + ((lane >> 3) & 1) * 8) * 2;
                uint32_t off = SMEM_SWIZZLE_128B((uint32_t)(row * 128 + colb));
                ldsm_x2(Bh[ni][0], Bh[ni][1], bB + off);
            }
            // A in two 64-row halves to cap register pressure
#pragma unroll
            for (int h = 0; h < 2; h++) {
                uint32_t Ah[4][4];
#pragma unroll
                for (int j = 0; j < 4; j++) {
                    int mi = h * 4 + j;
                    int row = wm + mi * 16 + (lane & 15);
                    int colb = (k0 + (lane >> 4) * 8) * 2;
                    uint32_t off = SMEM_SWIZZLE_128B((uint32_t)(row * 128 + colb));
                    ldsm_x4(Ah[j][0], Ah[j][1], Ah[j][2], Ah[j][3], aB + off);
                }
#pragma unroll
                for (int j = 0; j < 4; j++)
#pragma unroll
                    for (int ni = 0; ni < 4; ni++)
                        mma16816(acc[h * 4 + j][ni], Ah[j], Bh[ni][0], Bh[ni][1]);
            }
        }
    };

    // --- 3-stage pipeline, one __syncthreads per chunk ---
    load_chunk(0, 0);
    CP_COMMIT();
    if (nC > 1) { load_chunk(1, 1); CP_COMMIT(); }
    for (int c = 0; c < nC; c++) {
        if (c + 1 < nC) CP_WAIT_1(); else CP_WAIT_0();
        __syncthreads();
        if (c + 2 < nC) { load_chunk(c + 2, (c + 2) % 3); CP_COMMIT(); }
        compute_chunk(c % 3);
    }

    // --- epilogue ---
    int gq = lane >> 2;          // 0..7  (row group)
    int t4 = lane & 3;           // 0..3  (column pair)
    float dinv = FINAL ? g_denom_inv[e] : 0.f;
    const int* sTok = (const int*)smem;

#pragma unroll
    for (int mi = 0; mi < 8; mi++) {
        int rA = wm + mi * 16 + gq;       // local row for d0,d1
        int rB = rA + 8;                  // local row for d2,d3
        int tok0 = 0, tok1 = 0;
        float sc0 = 0.f, sc1 = 0.f;
        if (FINAL) {
            tok0 = sTok[rA]; tok1 = sTok[rB];
            if (tok0 >= 0) sc0 = g_logit[tok0] * dinv;
            if (tok1 >= 0) sc1 = g_logit[tok1] * dinv;
        }
#pragma unroll
        for (int ni = 0; ni < 4; ni++) {
            int gcol = bn + wn + ni * 8 + t4 * 2;
            float2 bv = __ldg((const float2*)(bias + (size_t)e * NTOT + gcol));
            float* d = acc[mi][ni];
            if (FINAL) {
                if (tok0 >= 0) {
                    float2 v = make_float2(sc0 * (d[0] + bv.x), sc0 * (d[1] + bv.y));
                    *(float2*)(fout + (size_t)tok0 * DDIM + gcol) = v;
                }
                if (tok1 >= 0) {
                    float2 v = make_float2(sc1 * (d[2] + bv.x), sc1 * (d[3] + bv.y));
                    *(float2*)(fout + (size_t)tok1 * DDIM + gcol) = v;
                }
            } else {
                float f0 = d[0] + bv.x; f0 = f0 > 0.f ? f0 : 0.f;
                float f1 = d[1] + bv.y; f1 = f1 > 0.f ? f1 : 0.f;
                float f2 = d[2] + bv.x; f2 = f2 > 0.f ? f2 : 0.f;
                float f3 = d[3] + bv.y; f3 = f3 > 0.f ? f3 : 0.f;

                __half2 h01 = __floats2half2_rn(f0, f1);
                __half2 h23 = __floats2half2_rn(f2, f3);
                *(uint32_t*)(g_H + (size_t)(row0 + rA) * FDIM + gcol) = *(uint32_t*)&h01;
                *(uint32_t*)(g_H + (size_t)(row0 + rB) * FDIM + gcol) = *(uint32_t*)&h23;
            }
        }
    }
}

// ---------------------------------------------------------------------------
extern "C" void kernel_launch(void* const* d_in, const int* in_sizes, int n_in,
                              void* d_out, int out_size) {
    const float* x  = (const float*)d_in[0];   // [N, D]
    const float* Wg = (const float*)d_in[1];   // [E, D]
    const float* W1 = (const float*)d_in[2];   // [E, D, F]
    const float* b1 = (const float*)d_in[3];   // [E, F]
    const float* W2 = (const float*)d_in[4];   // [E, F, D]
    const float* b2 = (const float*)d_in[5];   // [E, D]
    float* out = (float*)d_out;                // [N, D]

    cudaFuncSetAttribute(moe_gemm_kernel<DDIM, false>,
                         cudaFuncAttributeMaxDynamicSharedMemorySize, SMEM_GEMM_BYTES);
    cudaFuncSetAttribute(moe_gemm_kernel<FDIM, true>,
                         cudaFuncAttributeMaxDynamicSharedMemorySize, SMEM_GEMM_BYTES);

    router_kernel<<<N_TOK / 8, 256>>>(x, Wg);                       // 1 (also inits perm)
    setup_kernel<<<1, 256>>>();                                     // 2
    scatter_kernel<<<N_TOK / 256, 256>>>();                         // 3
    gather_x_kernel<<<PAD_ROWS, 128>>>(x);                          // 4
    trans_conv_kernel<<<dim3(2048, NEXP), 256>>>(W1, W2);           // 5

    moe_gemm_kernel<DDIM, false><<<dim3(MAX_TILES, FDIM / 128), 256, SMEM_GEMM_BYTES>>>(b1, nullptr);   // 6
    moe_gemm_kernel<FDIM, true><<<dim3(MAX_TILES, DDIM / 128), 256, SMEM_GEMM_BYTES>>>(b2, out);        // 7
}

// round 14
// speedup vs baseline: 2.3096x; 1.0398x over previous
#include <cuda_runtime.h>
#include <cuda_fp16.h>
#include <cstdint>

// ---------------- problem constants ----------------
#define N_TOK  16384
#define DDIM   512
#define FDIM   2048
#define NEXP   8
#define CAP    16384.0f
#define EPSV   1e-6f

#define PAD_ROWS (N_TOK + NEXP * 128)   // 17408
#define MAX_TILES (PAD_ROWS / 128)      // 136

// ---------------- scratch (device globals; 16B-access aligned) ----------------
__device__ unsigned char g_expert[N_TOK];
__device__ float g_logit[N_TOK];
__device__ float g_denom_inv[NEXP];
__device__ int   g_off[NEXP + 1];
__device__ int   g_ctr[NEXP];
__device__ int   g_perm[PAD_ROWS];

__device__ __align__(256) __half g_X[(size_t)PAD_ROWS * DDIM];        // gathered x, fp16
__device__ __align__(256) __half g_H[(size_t)PAD_ROWS * FDIM];        // hidden, fp16
__device__ __align__(256) __half g_W1T[(size_t)NEXP * FDIM * DDIM];   // [E][F][D]
__device__ __align__(256) __half g_W2T[(size_t)NEXP * DDIM * FDIM];   // [E][D][F]

// ---------------- helpers ----------------
__device__ __forceinline__ uint32_t smem_to_u32(const void* smem_ptr) {
    uint32_t addr;
    asm("{ .reg .u64 tmp; cvta.to.shared.u64 tmp, %1; cvt.u32.u64 %0, tmp; }"
        : "=r"(addr) : "l"(smem_ptr));
    return addr;
}

#define SMEM_SWIZZLE_128B(byte_offset) \
    ((byte_offset) ^ (((byte_offset) >> 3) & 0x70))

__device__ __forceinline__ void cp16(uint32_t dst, const void* src) {
    asm volatile("cp.async.cg.shared.global [%0], [%1], 16;"
                 :: "r"(dst), "l"(src) : "memory");
}
#define CP_COMMIT()  asm volatile("cp.async.commit_group;" ::: "memory")
#define CP_WAIT_1()  asm volatile("cp.async.wait_group 1;" ::: "memory")
#define CP_WAIT_0()  asm volatile("cp.async.wait_group 0;" ::: "memory")

__device__ __forceinline__ void ldsm_x4(uint32_t& r0, uint32_t& r1, uint32_t& r2,
                                        uint32_t& r3, uint32_t addr) {
    asm volatile("ldmatrix.sync.aligned.m8n8.x4.shared.b16 {%0,%1,%2,%3}, [%4];"
                 : "=r"(r0), "=r"(r1), "=r"(r2), "=r"(r3) : "r"(addr));
}
__device__ __forceinline__ void ldsm_x2(uint32_t& r0, uint32_t& r1, uint32_t addr) {
    asm volatile("ldmatrix.sync.aligned.m8n8.x2.shared.b16 {%0,%1}, [%2];"
                 : "=r"(r0), "=r"(r1) : "r"(addr));
}
__device__ __forceinline__ void mma16816(float* d, const uint32_t* a,
                                         uint32_t b0, uint32_t b1) {
    asm volatile(
        "mma.sync.aligned.m16n8k16.row.col.f32.f16.f16.f32 "
        "{%0,%1,%2,%3},{%4,%5,%6,%7},{%8,%9},{%0,%1,%2,%3};"
        : "+f"(d[0]), "+f"(d[1]), "+f"(d[2]), "+f"(d[3])
        : "r"(a[0]), "r"(a[1]), "r"(a[2]), "r"(a[3]), "r"(b0), "r"(b1));
}

// ---------------------------------------------------------------------------
// 1) router (+ perm init folded in): logits = x @ Wg^T, top-1 per token
// ---------------------------------------------------------------------------
__global__ __launch_bounds__(256) void router_kernel(const float* __restrict__ x,
                                                     const float* __restrict__ Wg) {
    int gidx = blockIdx.x * 256 + threadIdx.x;
    if (gidx < PAD_ROWS) g_perm[gidx] = -1;

    __shared__ float sWg[NEXP * DDIM];
    int tid = threadIdx.x;
    for (int i = tid; i < NEXP * DDIM; i += 256) sWg[i] = Wg[i];
    __syncthreads();

    int warp = tid >> 5, lane = tid & 31;
    int token = blockIdx.x * 8 + warp;
    if (token >= N_TOK) return;

    const float* xr = x + (size_t)token * DDIM;
    float acc[NEXP];
#pragma unroll
    for (int e = 0; e < NEXP; e++) acc[e] = 0.f;
    for (int k = lane; k < DDIM; k += 32) {
        float xv = xr[k];
#pragma unroll
        for (int e = 0; e < NEXP; e++) acc[e] += xv * sWg[e * DDIM + k];
    }
#pragma unroll
    for (int e = 0; e < NEXP; e++) {
#pragma unroll
        for (int off = 16; off > 0; off >>= 1)
            acc[e] += __shfl_xor_sync(0xFFFFFFFF, acc[e], off);
    }
    if (lane == 0) {
        int best = 0;
#pragma unroll
        for (int e = 1; e < NEXP; e++)
            if (acc[e] > acc[best]) best = e;
        g_expert[token] = (unsigned char)best;
        g_logit[token]  = acc[best];
    }
}

// ---------------------------------------------------------------------------
// 2) setup (single block, deterministic tree reduction); segments pad to 128
// ---------------------------------------------------------------------------
__global__ __launch_bounds__(256) void setup_kernel() {
    __shared__ float sden[NEXP][256];
    __shared__ int   scnt[NEXP][256];
    int tid = threadIdx.x;

    float den[NEXP]; int cnt[NEXP];
#pragma unroll
    for (int e = 0; e < NEXP; e++) { den[e] = 0.f; cnt[e] = 0; }
    for (int t = tid; t < N_TOK; t += 256) {
        int e = g_expert[t];
        den[e] += g_logit[t];
        cnt[e]++;
    }
#pragma unroll
    for (int e = 0; e < NEXP; e++) { sden[e][tid] = den[e]; scnt[e][tid] = cnt[e]; }
    __syncthreads();
    for (int s = 128; s > 0; s >>= 1) {
        if (tid < s) {
#pragma unroll
            for (int e = 0; e < NEXP; e++) {
                sden[e][tid] += sden[e][tid + s];
                scnt[e][tid] += scnt[e][tid + s];
            }
        }
        __syncthreads();
    }
    if (tid == 0) {
        int off = 0;
        for (int e = 0; e < NEXP; e++) {
            g_denom_inv[e] = CAP / (sden[e][0] + EPSV);
            g_off[e] = off;
            g_ctr[e] = off;
            off += ((scnt[e][0] + 127) >> 7) << 7;
        }
        g_off[NEXP] = off;
    }
}

// ---------------------------------------------------------------------------
// 3) scatter
// ---------------------------------------------------------------------------
__global__ void scatter_kernel() {
    int t = blockIdx.x * blockDim.x + threadIdx.x;
    if (t >= N_TOK) return;
    int e = g_expert[t];
    int pos = atomicAdd(&g_ctr[e], 1);
    g_perm[pos] = t;
}

// ---------------------------------------------------------------------------
// 4) gather x into sorted order, convert to fp16
// ---------------------------------------------------------------------------
__global__ __launch_bounds__(128) void gather_x_kernel(const float* __restrict__ x) {
    int r = blockIdx.x;
    int t = threadIdx.x;
    int tok = g_perm[r];
    float4 v = make_float4(0.f, 0.f, 0.f, 0.f);
    if (tok >= 0) v = *(const float4*)(x + (size_t)tok * DDIM + t * 4);

    __half2 h01 = __floats2half2_rn(v.x, v.y);
    __half2 h23 = __floats2half2_rn(v.z, v.w);
    uint2 hh;
    hh.x = *(uint32_t*)&h01; hh.y = *(uint32_t*)&h23;
    *(uint2*)(g_X + (size_t)r * DDIM + t * 4) = hh;
}

// ---------------------------------------------------------------------------
// 5) fused transpose+convert of BOTH weights (one launch, fp16 single):
//    W1 [E][D][F] -> W1T [E][F][D]   (tiles 0..1023)
//    W2 [E][F][D] -> W2T [E][D][F]   (tiles 1024..2047)
// ---------------------------------------------------------------------------
__global__ __launch_bounds__(256) void trans_conv_kernel(const float* __restrict__ W1,
                                                         const float* __restrict__ W2) {
    __shared__ float tile[32][33];
    int t = blockIdx.x;
    int e = blockIdx.y;

    const float* in;
    __half* out;
    int R, C, c0, r0;
    if (t < 1024) {                    // W1: R=DDIM, C=FDIM
        in = W1; out = g_W1T;
        R = DDIM; C = FDIM;
        c0 = (t & 63) * 32;
        r0 = (t >> 6) * 32;
    } else {                           // W2: R=FDIM, C=DDIM
        int u = t - 1024;
        in = W2; out = g_W2T;
        R = FDIM; C = DDIM;
        c0 = (u & 15) * 32;
        r0 = (u >> 4) * 32;
    }

    int tx = threadIdx.x & 31;
    int ty8 = threadIdx.x >> 5;

    const float* src = in + ((size_t)e * R + r0) * C + c0;
#pragma unroll
    for (int i = 0; i < 32; i += 8)
        tile[ty8 + i][tx] = src[(size_t)(ty8 + i) * C + tx];
    __syncthreads();

    size_t ob = ((size_t)e * C + c0) * R + r0;
#pragma unroll
    for (int i = 0; i < 32; i += 8)
        out[ob + (size_t)(ty8 + i) * R + tx] = __float2half_rn(tile[tx][ty8 + i]);
}

// ---------------------------------------------------------------------------
// HMMA grouped GEMM, pure fp16 single pass, BM=128 x BN=128, 2 CTAs/SM:
//   C[128 x 128 tile] = A[128 x KTOT] @ B^T  (B: [N][K] K-major)
// cp.async 3-stage pipeline, one sync per chunk; ldmatrix + mma.sync;
// 8 warps, warp tile 64 x 32 (2 m-warps x 4 n-warps).
// __launch_bounds__(256, 2) caps regs at 128 so two CTAs co-reside per SM:
// one CTA's compute hides the other's fill/sync/epilogue bubbles (4 warps/SMSP).
//   FINAL=false: A = g_X (sorted), B = W1T, epilogue relu(+b1) -> g_H fp16
//   FINAL=true : A = g_H,          B = W2T, epilogue scale*(+b2) -> scatter to out
//
// smem per stage (32KB): A 16K | B 16K
// dynamic layout: [0,512) token ids (FINAL) | [1024 + p*32768) stages (3)
// total 97KB/CTA -> 194KB for 2 CTAs (fits 227KB)
// ---------------------------------------------------------------------------
#define STAGE_BYTES 32768
#define SMEM_GEMM_BYTES (1024 + 3 * STAGE_BYTES)   // 99328

template<int KTOT, bool FINAL>
__global__ __launch_bounds__(256, 2) void moe_gemm_kernel(
    const float* __restrict__ bias,   // [E][NTOT]
    float* __restrict__ fout)         // FINAL: [N_TOK][DDIM]
{
    constexpr int NTOT = FINAL ? DDIM : FDIM;
    extern __shared__ char smem[];
    uint32_t sbase = smem_to_u32(smem);
    int tid = threadIdx.x;
    int lane = tid & 31, wid = tid >> 5;

    int row0 = blockIdx.x * 128;
    int total = g_off[NEXP];
    if (row0 >= total) return;
    int e = 0;
    while (g_off[e + 1] <= row0) e++;
    int bn = blockIdx.y * 128;

    if (FINAL && tid < 128) ((int*)smem)[tid] = g_perm[row0 + tid];

    const __half* A = (FINAL ? g_H : g_X) + (size_t)row0 * KTOT;
    const __half* B = (FINAL ? g_W2T : g_W1T) + ((size_t)e * NTOT + bn) * KTOT;

    const int nC = KTOT / 64;

    // warp tile: 64 (m) x 32 (n); warps laid out 2 (m) x 4 (n)
    int wm = (wid & 1) * 64;
    int wn = (wid >> 1) * 32;

    float acc[4][4][4];
#pragma unroll
    for (int mi = 0; mi < 4; mi++)
#pragma unroll
        for (int ni = 0; ni < 4; ni++)
#pragma unroll
            for (int q = 0; q < 4; q++) acc[mi][ni][q] = 0.f;

    // --- async load of one 64-wide K chunk into stage p ---
    auto load_chunk = [&](int c, int p) {
        int kt = c * 64;
        uint32_t base = sbase + 1024 + p * STAGE_BYTES;
#pragma unroll
        for (int i = 0; i < 4; i++) {
            int u = tid + i * 256;          // 0..1023
            int r = u >> 3, s = u & 7;      // row, 16B-chunk
            uint32_t sw = SMEM_SWIZZLE_128B((uint32_t)(r * 128 + s * 16));
            size_t goff = (size_t)r * KTOT + kt + s * 8;
            cp16(base +         sw, A + goff);
            cp16(base + 16384 + sw, B + goff);
        }
    };

    // --- compute one staged chunk (4 k-steps of 16) ---
    auto compute_chunk = [&](int p) {
        uint32_t aB = sbase + 1024 + p * STAGE_BYTES;
        uint32_t bB = aB + 16384;
#pragma unroll
        for (int ks = 0; ks < 4; ks++) {
            int k0 = ks * 16;
            uint32_t Ah[4][4];
#pragma unroll
            for (int mi = 0; mi < 4; mi++) {
                int row = wm + mi * 16 + (lane & 15);
                int colb = (k0 + (lane >> 4) * 8) * 2;
                uint32_t off = SMEM_SWIZZLE_128B((uint32_t)(row * 128 + colb));
                ldsm_x4(Ah[mi][0], Ah[mi][1], Ah[mi][2], Ah[mi][3], aB + off);
            }
            uint32_t Bh[4][2];
#pragma unroll
            for (int ni = 0; ni < 4; ni++) {
                int row = wn + ni * 8 + (lane & 7);
                int colb = (k0 + ((lane >> 3) & 1) * 8) * 2;
                uint32_t off = SMEM_SWIZZLE_128B((uint32_t)(row * 128 + colb));
                ldsm_x2(Bh[ni][0], Bh[ni][1], bB + off);
            }
#pragma unroll
            for (int mi = 0; mi < 4; mi++)
#pragma unroll
                for (int ni = 0; ni < 4; ni++)
                    mma16816(acc[mi][ni], Ah[mi], Bh[ni][0], Bh[ni][1]);
        }
    };

    // --- 3-stage pipeline, one __syncthreads per chunk ---
    load_chunk(0, 0);
    CP_COMMIT();
    if (nC > 1) { load_chunk(1, 1); CP_COMMIT(); }
    for (int c = 0; c < nC; c++) {
        if (c + 1 < nC) CP_WAIT_1(); else CP_WAIT_0();
        __syncthreads();
        if (c + 2 < nC) { load_chunk(c + 2, (c + 2) % 3); CP_COMMIT(); }
        compute_chunk(c % 3);
    }

    // --- epilogue ---
    int gq = lane >> 2;          // 0..7  (row group)
    int t4 = lane & 3;           // 0..3  (column pair)
    float dinv = FINAL ? g_denom_inv[e] : 0.f;
    const int* sTok = (const int*)smem;

#pragma unroll
    for (int mi = 0; mi < 4; mi++) {
        int rA = wm + mi * 16 + gq;       // local row for d0,d1
        int rB = rA + 8;                  // local row for d2,d3
        int tok0 = 0, tok1 = 0;
        float sc0 = 0.f, sc1 = 0.f;
        if (FINAL) {
            tok0 = sTok[rA]; tok1 = sTok[rB];
            if (tok0 >= 0) sc0 = g_logit[tok0] * dinv;
            if (tok1 >= 0) sc1 = g_logit[tok1] * dinv;
        }
#pragma unroll
        for (int ni = 0; ni < 4; ni++) {
            int gcol = bn + wn + ni * 8 + t4 * 2;
            float2 bv = __ldg((const float2*)(bias + (size_t)e * NTOT + gcol));
            float* d = acc[mi][ni];
            if (FINAL) {
                if (tok0 >= 0) {
                    float2 v = make_float2(sc0 * (d[0] + bv.x), sc0 * (d[1] + bv.y));
                    *(float2*)(fout + (size_t)tok0 * DDIM + gcol) = v;
                }
                if (tok1 >= 0) {
                    float2 v = make_float2(sc1 * (d[2] + bv.x), sc1 * (d[3] + bv.y));
                    *(float2*)(fout + (size_t)tok1 * DDIM + gcol) = v;
                }
            } else {
                float f0 = d[0] + bv.x; f0 = f0 > 0.f ? f0 : 0.f;
                float f1 = d[1] + bv.y; f1 = f1 > 0.f ? f1 : 0.f;
                float f2 = d[2] + bv.x; f2 = f2 > 0.f ? f2 : 0.f;
                float f3 = d[3] + bv.y; f3 = f3 > 0.f ? f3 : 0.f;

                __half2 h01 = __floats2half2_rn(f0, f1);
                __half2 h23 = __floats2half2_rn(f2, f3);
                *(uint32_t*)(g_H + (size_t)(row0 + rA) * FDIM + gcol) = *(uint32_t*)&h01;
                *(uint32_t*)(g_H + (size_t)(row0 + rB) * FDIM + gcol) = *(uint32_t*)&h23;
            }
        }
    }
}

// ---------------------------------------------------------------------------
extern "C" void kernel_launch(void* const* d_in, const int* in_sizes, int n_in,
                              void* d_out, int out_size) {
    const float* x  = (const float*)d_in[0];   // [N, D]
    const float* Wg = (const float*)d_in[1];   // [E, D]
    const float* W1 = (const float*)d_in[2];   // [E, D, F]
    const float* b1 = (const float*)d_in[3];   // [E, F]
    const float* W2 = (const float*)d_in[4];   // [E, F, D]
    const float* b2 = (const float*)d_in[5];   // [E, D]
    float* out = (float*)d_out;                // [N, D]

    cudaFuncSetAttribute(moe_gemm_kernel<DDIM, false>,
                         cudaFuncAttributeMaxDynamicSharedMemorySize, SMEM_GEMM_BYTES);
    cudaFuncSetAttribute(moe_gemm_kernel<FDIM, true>,
                         cudaFuncAttributeMaxDynamicSharedMemorySize, SMEM_GEMM_BYTES);

    router_kernel<<<N_TOK / 8, 256>>>(x, Wg);                       // 1 (also inits perm)
    setup_kernel<<<1, 256>>>();                                     // 2
    scatter_kernel<<<N_TOK / 256, 256>>>();                         // 3
    gather_x_kernel<<<PAD_ROWS, 128>>>(x);                          // 4
    trans_conv_kernel<<<dim3(2048, NEXP), 256>>>(W1, W2);           // 5

    moe_gemm_kernel<DDIM, false><<<dim3(MAX_TILES, FDIM / 128), 256, SMEM_GEMM_BYTES>>>(b1, nullptr);   // 6
    moe_gemm_kernel<FDIM, true><<<dim3(MAX_TILES, DDIM / 128), 256, SMEM_GEMM_BYTES>>>(b2, out);        // 7
}